// round 3
// baseline (speedup 1.0000x reference)
#include <cuda_runtime.h>
#include <cuda_bf16.h>
#include <cstdint>

#define HD   128
#define NMAX 100000
#define EMAX 1700000
#define EPS  1e-5f
#define MT   128        // nodes per block in fused layer kernel
#define TBS  132        // Tb row stride (pad: 132 mod 32 = 4, float4-aligned)

typedef unsigned long long ull;

// ---------------- scratch (__device__ globals; no runtime allocation) ----------
__device__ int   g_deg [6 * NMAX];                      // [out0,in0,out1,in1,out2,in2] x N
__device__ float g_rs  [6 * NMAX];                      // rsqrt(max(deg,1))
__device__ int   g_off [3 * (NMAX + 1)];                // CSR row offsets (by dst), per relation
__device__ int   g_cur [3 * NMAX];                      // fill cursors
__device__ int   g_csum[3 * 512];                       // chunk partial sums for scan
__device__ int2  g_csr [3 * (size_t)EMAX];              // (src, bits(rs_out[src])) sorted by dst
__device__ float g_h   [(size_t)NMAX * HD];             // layer-0 output

// ---------------- f32x2 helpers (sm_103a packed fp32) ---------------------------
__device__ __forceinline__ ull pack2(float a) {
    ull r; asm("mov.b64 %0, {%1, %1};" : "=l"(r) : "f"(a)); return r;
}
__device__ __forceinline__ ull pack2f(float lo, float hi) {
    ull r; asm("mov.b64 %0, {%1, %2};" : "=l"(r) : "f"(lo), "f"(hi)); return r;
}
__device__ __forceinline__ float2 unpack2(ull v) {
    float2 r; asm("mov.b64 {%0, %1}, %2;" : "=f"(r.x), "=f"(r.y) : "l"(v)); return r;
}
__device__ __forceinline__ void fma2(ull& d, ull a, ull b) {
    asm("fma.rn.f32x2 %0, %1, %2, %0;" : "+l"(d) : "l"(a), "l"(b));
}

// ---------------- small utility kernels ---------------------------------------
__global__ void zero_int_kernel(int* __restrict__ p, int count) {
    int i = blockIdx.x * blockDim.x + threadIdx.x;
    if (i < count) p[i] = 0;
}

__global__ void count_pair_kernel(const int* __restrict__ src, const int* __restrict__ dst,
                                  int* __restrict__ dout, int* __restrict__ din, int e) {
    int i = blockIdx.x * blockDim.x + threadIdx.x;
    if (i >= e) return;
    atomicAdd(dout + src[i], 1);
    atomicAdd(din  + dst[i], 1);
}

__global__ void rs_kernel(const int* __restrict__ deg, float* __restrict__ rs, int count) {
    int i = blockIdx.x * blockDim.x + threadIdx.x;
    if (i < count) {
        int d = deg[i];
        rs[i] = rsqrtf((float)(d < 1 ? 1 : d));
    }
}

// ---------------- CSR build: 2-level exclusive scan + bucket fill --------------
__global__ void chunk_sum_kernel(const int* __restrict__ deg, int* __restrict__ csum, int n) {
    __shared__ int s[256];
    int i = blockIdx.x * 256 + threadIdx.x;
    s[threadIdx.x] = (i < n) ? deg[i] : 0;
    __syncthreads();
    #pragma unroll
    for (int st = 128; st > 0; st >>= 1) {
        if (threadIdx.x < st) s[threadIdx.x] += s[threadIdx.x + st];
        __syncthreads();
    }
    if (threadIdx.x == 0) csum[blockIdx.x] = s[0];
}

__global__ void scan_chunks_kernel(int* __restrict__ csum, int nc) {
    __shared__ int s[512];
    int t = threadIdx.x;
    int v0 = (t < nc) ? csum[t] : 0;
    s[t] = v0;
    __syncthreads();
    #pragma unroll
    for (int off = 1; off < 512; off <<= 1) {
        int v = (t >= off) ? s[t - off] : 0;
        __syncthreads();
        s[t] += v;
        __syncthreads();
    }
    if (t < nc) csum[t] = s[t] - v0;   // exclusive
}

__global__ void write_offsets_kernel(const int* __restrict__ deg, const int* __restrict__ csum,
                                     int* __restrict__ off, int* __restrict__ cur, int n) {
    __shared__ int s[256];
    int t = threadIdx.x;
    int i = blockIdx.x * 256 + t;
    int d = (i < n) ? deg[i] : 0;
    s[t] = d;
    __syncthreads();
    #pragma unroll
    for (int o = 1; o < 256; o <<= 1) {
        int v = (t >= o) ? s[t - o] : 0;
        __syncthreads();
        s[t] += v;
        __syncthreads();
    }
    int excl = s[t] - d + csum[blockIdx.x];
    if (i < n) {
        off[i] = excl;
        cur[i] = excl;
        if (i == n - 1) off[n] = excl + d;
    }
}

__global__ void csr_fill_kernel(const int* __restrict__ src, const int* __restrict__ dst,
                                const float* __restrict__ rs_out,
                                int* __restrict__ cur, int2* __restrict__ csr, int e) {
    int i = blockIdx.x * blockDim.x + threadIdx.x;
    if (i >= e) return;
    int s = src[i];
    float c = __ldg(rs_out + s);
    int slot = atomicAdd(cur + dst[i], 1);
    csr[slot] = make_int2(s, __float_as_int(c));
}

// ---------------- fused per-layer kernel ----------------------------------------
// Block = 128 nodes x 128 outputs, 256 threads.
// For each relation: gather normalized neighbor sum into Tb smem, then f32x2 GEMM
// against Wg_r. Then FC GEMM + ReLU + BN epilogue. No global intermediate.

__device__ __forceinline__ void load_ws(float* __restrict__ Ws, const float* __restrict__ src, int tid) {
    int kw = tid >> 3, jq = tid & 7;
    const float4* wp = (const float4*)(src + (size_t)kw * HD + jq * 16);
    float4 w0 = __ldg(wp), w1 = __ldg(wp + 1), w2 = __ldg(wp + 2), w3 = __ldg(wp + 3);
    float* ws = &Ws[kw * HD + jq * 16];
    *(float4*)(ws)      = w0;
    *(float4*)(ws + 4)  = w1;
    *(float4*)(ws + 8)  = w2;
    *(float4*)(ws + 12) = w3;
}

__device__ __forceinline__ void mma_chunk(const float* __restrict__ Tb, const float* __restrict__ Ws,
                                          ull acc[8][4], int m0, int jA, int jB, int kb) {
    #pragma unroll
    for (int k4 = 0; k4 < 8; k4++) {
        float4 av[8];
        #pragma unroll
        for (int i = 0; i < 8; i++)
            av[i] = *(const float4*)&Tb[(m0 + i) * TBS + kb + k4 * 4];
        #pragma unroll
        for (int kk = 0; kk < 4; kk++) {
            int k = k4 * 4 + kk;
            ulonglong2 b0 = *(const ulonglong2*)&Ws[k * HD + jA];
            ulonglong2 b1 = *(const ulonglong2*)&Ws[k * HD + jB];
            #pragma unroll
            for (int i = 0; i < 8; i++) {
                float a = (kk == 0) ? av[i].x : (kk == 1) ? av[i].y : (kk == 2) ? av[i].z : av[i].w;
                ull p = pack2(a);
                fma2(acc[i][0], p, b0.x);
                fma2(acc[i][1], p, b0.y);
                fma2(acc[i][2], p, b1.x);
                fma2(acc[i][3], p, b1.y);
            }
        }
    }
}

__global__ __launch_bounds__(256, 2) void layer_kernel(
    const float* __restrict__ hin,
    const int2* __restrict__ csr,      // [3][EMAX]
    const int* __restrict__ off,       // [3][NMAX+1]
    const float* __restrict__ rs,      // g_rs base; rs_in of rel r at (2r+1)*n
    const float* __restrict__ Wg,      // [3][HD][HD]
    const float* __restrict__ bg,      // [3][HD]
    const float* __restrict__ Wfc,     // [HD][HD]
    const float* __restrict__ bfc,     // [HD]
    const float* __restrict__ gamma, const float* __restrict__ beta,
    const float* __restrict__ mean,  const float* __restrict__ var,
    float* __restrict__ out, int n)
{
    extern __shared__ float smem[];
    float* Ws = smem;                  // 32*128 = 16 KB
    float* Tb = smem + 32 * HD;        // 128*132 = 67.6 KB

    const int tid  = threadIdx.x;
    const int lane = tid & 31;
    const int wrp  = tid >> 5;
    const int tn   = tid & 15;
    const int tm   = tid >> 4;
    const int jA   = tn * 4;
    const int jB   = 64 + tn * 4;
    const int m0   = tm * 8;
    const int bn0  = blockIdx.x * MT;

    ull acc[8][4];
    #pragma unroll
    for (int p = 0; p < 4; p++) {
        int j = (p < 2) ? (jA + p * 2) : (jB + (p - 2) * 2);
        float blo = __ldg(bg + j)     + __ldg(bg + HD + j)     + __ldg(bg + 2 * HD + j);
        float bhi = __ldg(bg + j + 1) + __ldg(bg + HD + j + 1) + __ldg(bg + 2 * HD + j + 1);
        ull b = pack2f(blo, bhi);
        #pragma unroll
        for (int i = 0; i < 8; i++) acc[i][p] = b;
    }

    // ---------------- phase 1: per relation gather -> GEMM ---------------------
    for (int r = 0; r < 3; r++) {
        __syncthreads();                       // Tb free (prev compute / init done)
        const int2*  cp   = csr + (size_t)r * EMAX;
        const int*   op   = off + (size_t)r * (NMAX + 1);
        const float* ri_p = rs + (size_t)(2 * r + 1) * n;

        #pragma unroll 1
        for (int i = 0; i < 16; i++) {
            int m = wrp * 16 + i;
            int g = bn0 + m;
            float4 a = make_float4(0.f, 0.f, 0.f, 0.f);
            if (g < n) {
                int e0 = __ldg(op + g), e1 = __ldg(op + g + 1);
                int e = e0;
                for (; e + 1 < e1; e += 2) {
                    int2 ea = __ldg(cp + e), eb = __ldg(cp + e + 1);
                    float ca = __int_as_float(ea.y), cb = __int_as_float(eb.y);
                    float4 va = __ldg((const float4*)(hin + (size_t)ea.x * HD) + lane);
                    float4 vb = __ldg((const float4*)(hin + (size_t)eb.x * HD) + lane);
                    a.x = fmaf(va.x, ca, a.x); a.y = fmaf(va.y, ca, a.y);
                    a.z = fmaf(va.z, ca, a.z); a.w = fmaf(va.w, ca, a.w);
                    a.x = fmaf(vb.x, cb, a.x); a.y = fmaf(vb.y, cb, a.y);
                    a.z = fmaf(vb.z, cb, a.z); a.w = fmaf(vb.w, cb, a.w);
                }
                if (e < e1) {
                    int2 ea = __ldg(cp + e);
                    float ca = __int_as_float(ea.y);
                    float4 va = __ldg((const float4*)(hin + (size_t)ea.x * HD) + lane);
                    a.x = fmaf(va.x, ca, a.x); a.y = fmaf(va.y, ca, a.y);
                    a.z = fmaf(va.z, ca, a.z); a.w = fmaf(va.w, ca, a.w);
                }
                float riv = __ldg(ri_p + g);
                a.x *= riv; a.y *= riv; a.z *= riv; a.w *= riv;
            }
            *(float4*)&Tb[m * TBS + lane * 4] = a;
        }
        __syncthreads();                       // gather visible

        for (int c = 0; c < 4; c++) {
            if (c) __syncthreads();            // prev chunk compute done before Ws overwrite
            load_ws(Ws, Wg + ((size_t)r * HD + c * 32) * HD, tid);
            __syncthreads();
            mma_chunk(Tb, Ws, acc, m0, jA, jB, c * 32);
        }
    }

    // ---------------- transition: t -> Tb --------------------------------------
    __syncthreads();
    #pragma unroll
    for (int i = 0; i < 8; i++) {
        float2 u0 = unpack2(acc[i][0]), u1 = unpack2(acc[i][1]);
        float2 u2 = unpack2(acc[i][2]), u3 = unpack2(acc[i][3]);
        *(float4*)&Tb[(m0 + i) * TBS + jA] = make_float4(u0.x, u0.y, u1.x, u1.y);
        *(float4*)&Tb[(m0 + i) * TBS + jB] = make_float4(u2.x, u2.y, u3.x, u3.y);
    }
    #pragma unroll
    for (int p = 0; p < 4; p++) {
        int j = (p < 2) ? (jA + p * 2) : (jB + (p - 2) * 2);
        ull b = pack2f(__ldg(bfc + j), __ldg(bfc + j + 1));
        #pragma unroll
        for (int i = 0; i < 8; i++) acc[i][p] = b;
    }

    // ---------------- phase 2: y = t @ Wfc + bfc --------------------------------
    for (int c = 0; c < 4; c++) {
        __syncthreads();                       // covers t writes (c=0) and Ws reuse (c>0)
        load_ws(Ws, Wfc + (size_t)c * 32 * HD, tid);
        __syncthreads();
        mma_chunk(Tb, Ws, acc, m0, jA, jB, c * 32);
    }

    // ---------------- epilogue: ReLU + BatchNorm(eval) --------------------------
    #pragma unroll
    for (int p = 0; p < 4; p++) {
        int j = (p < 2) ? (jA + p * 2) : (jB + (p - 2) * 2);
        float sc0 = __ldg(gamma + j)     * rsqrtf(__ldg(var + j)     + EPS);
        float sc1 = __ldg(gamma + j + 1) * rsqrtf(__ldg(var + j + 1) + EPS);
        float sh0 = __ldg(beta + j)     - __ldg(mean + j)     * sc0;
        float sh1 = __ldg(beta + j + 1) - __ldg(mean + j + 1) * sc1;
        #pragma unroll
        for (int i = 0; i < 8; i++) {
            float2 u = unpack2(acc[i][p]);
            float r0 = fmaxf(u.x, 0.f) * sc0 + sh0;
            float r1 = fmaxf(u.y, 0.f) * sc1 + sh1;
            acc[i][p] = pack2f(r0, r1);
        }
    }
    #pragma unroll
    for (int i = 0; i < 8; i++) {
        int node = bn0 + m0 + i;
        if (node < n) {
            float* opo = out + (size_t)node * HD;
            float2 u0 = unpack2(acc[i][0]), u1 = unpack2(acc[i][1]);
            float2 u2 = unpack2(acc[i][2]), u3 = unpack2(acc[i][3]);
            *(float4*)(opo + jA) = make_float4(u0.x, u0.y, u1.x, u1.y);
            *(float4*)(opo + jB) = make_float4(u2.x, u2.y, u3.x, u3.y);
        }
    }
}

// ---------------- launch --------------------------------------------------------
extern "C" void kernel_launch(void* const* d_in, const int* in_sizes, int n_in,
                              void* d_out, int out_size)
{
    const float* x     = (const float*)d_in[0];
    const int* srcs[3] = {(const int*)d_in[1], (const int*)d_in[3], (const int*)d_in[5]};
    const int* dsts[3] = {(const int*)d_in[2], (const int*)d_in[4], (const int*)d_in[6]};
    const float* Wgl[2] = {(const float*)d_in[7], (const float*)d_in[9]};
    const float* bgl[2] = {(const float*)d_in[8], (const float*)d_in[10]};
    const float* Wfc   = (const float*)d_in[11];
    const float* bfc   = (const float*)d_in[12];
    const float* gamma = (const float*)d_in[13];
    const float* beta  = (const float*)d_in[14];
    const float* mean  = (const float*)d_in[15];
    const float* var   = (const float*)d_in[16];

    int n = in_sizes[0] / HD;
    int es[3] = {in_sizes[1], in_sizes[3], in_sizes[5]};

    int *p_deg, *p_off, *p_cur, *p_csum;
    int2* p_csr;
    float *p_rs, *p_h;
    cudaGetSymbolAddress((void**)&p_deg,  g_deg);
    cudaGetSymbolAddress((void**)&p_rs,   g_rs);
    cudaGetSymbolAddress((void**)&p_off,  g_off);
    cudaGetSymbolAddress((void**)&p_cur,  g_cur);
    cudaGetSymbolAddress((void**)&p_csum, g_csum);
    cudaGetSymbolAddress((void**)&p_csr,  g_csr);
    cudaGetSymbolAddress((void**)&p_h,    g_h);

    const int NT = 256;
    const int nchunks = (n + 255) / 256;
    const int SMEM_BYTES = (32 * HD + MT * TBS) * 4;   // 83968 B

    cudaFuncSetAttribute(layer_kernel, cudaFuncAttributeMaxDynamicSharedMemorySize, SMEM_BYTES);

    // 1) degrees -> rsqrt normalizers
    zero_int_kernel<<<(6 * n + NT - 1) / NT, NT>>>(p_deg, 6 * n);
    for (int r = 0; r < 3; r++)
        count_pair_kernel<<<(es[r] + NT - 1) / NT, NT>>>(
            srcs[r], dsts[r], p_deg + (size_t)2 * r * n, p_deg + (size_t)(2 * r + 1) * n, es[r]);
    rs_kernel<<<(6 * n + NT - 1) / NT, NT>>>(p_deg, p_rs, 6 * n);

    // 2) CSR by dst (entries carry rs_out[src]); reused by both layers
    for (int r = 0; r < 3; r++) {
        const int* deg_in = p_deg + (size_t)(2 * r + 1) * n;
        int* off  = p_off  + (size_t)r * (NMAX + 1);
        int* cur  = p_cur  + (size_t)r * NMAX;
        int* csum = p_csum + (size_t)r * 512;
        int2* csr = p_csr  + (size_t)r * EMAX;
        chunk_sum_kernel<<<nchunks, 256>>>(deg_in, csum, n);
        scan_chunks_kernel<<<1, 512>>>(csum, nchunks);
        write_offsets_kernel<<<nchunks, 256>>>(deg_in, csum, off, cur, n);
        csr_fill_kernel<<<(es[r] + NT - 1) / NT, NT>>>(
            srcs[r], dsts[r], p_rs + (size_t)2 * r * n, cur, csr, es[r]);
    }

    // 3) fused layers
    int blocks = (n + MT - 1) / MT;
    layer_kernel<<<blocks, 256, SMEM_BYTES>>>(
        x, p_csr, p_off, p_rs,
        Wgl[0], bgl[0], Wfc, bfc,
        gamma, beta, mean, var,
        p_h, n);
    layer_kernel<<<blocks, 256, SMEM_BYTES>>>(
        p_h, p_csr, p_off, p_rs,
        Wgl[1], bgl[1], Wfc + (size_t)HD * HD, bfc + HD,
        gamma + HD, beta + HD, mean + HD, var + HD,
        (float*)d_out, n);
}

// round 4
// speedup vs baseline: 1.2573x; 1.2573x over previous
#include <cuda_runtime.h>
#include <cuda_bf16.h>
#include <cstdint>

#define HD   128
#define NMAX 100000
#define EMAX 1700000
#define EPS  1e-5f
#define TBD  68         // phase-1 dup A row stride (floats): 32k*2 + 4 pad
#define TB2  132        // phase-2 t row stride

typedef unsigned long long ull;

// ---------------- scratch (__device__ globals; no runtime allocation) ----------
__device__ int   g_deg [6 * NMAX];                      // [out0,in0,out1,in1,out2,in2] x N
__device__ float g_rs  [6 * NMAX];                      // rsqrt(max(deg,1))
__device__ int   g_off [3 * (NMAX + 1)];                // CSR row offsets (by dst), per relation
__device__ int   g_cur [3 * NMAX];                      // fill cursors
__device__ int   g_csum[3 * 512];                       // chunk partial sums for scan
__device__ int2  g_csr [3 * (size_t)EMAX];              // (src, bits(rs_out[src])) sorted by dst
__device__ float g_agg [(size_t)3 * NMAX * HD];         // per-relation normalized aggregation
__device__ float g_h   [(size_t)NMAX * HD];             // layer-0 output

// ---------------- f32x2 helpers (sm_103a packed fp32) ---------------------------
__device__ __forceinline__ ull pack2(float a) {
    ull r; asm("mov.b64 %0, {%1, %1};" : "=l"(r) : "f"(a)); return r;
}
__device__ __forceinline__ ull pack2f(float lo, float hi) {
    ull r; asm("mov.b64 %0, {%1, %2};" : "=l"(r) : "f"(lo), "f"(hi)); return r;
}
__device__ __forceinline__ float2 unpack2(ull v) {
    float2 r; asm("mov.b64 {%0, %1}, %2;" : "=f"(r.x), "=f"(r.y) : "l"(v)); return r;
}
__device__ __forceinline__ void fma2(ull& d, ull a, ull b) {
    asm("fma.rn.f32x2 %0, %1, %2, %0;" : "+l"(d) : "l"(a), "l"(b));
}

// ---------------- small utility kernels ---------------------------------------
__global__ void zero_int_kernel(int* __restrict__ p, int count) {
    int i = blockIdx.x * blockDim.x + threadIdx.x;
    if (i < count) p[i] = 0;
}

__global__ void count_pair_kernel(const int* __restrict__ src, const int* __restrict__ dst,
                                  int* __restrict__ dout, int* __restrict__ din, int e) {
    int i = blockIdx.x * blockDim.x + threadIdx.x;
    if (i >= e) return;
    atomicAdd(dout + src[i], 1);
    atomicAdd(din  + dst[i], 1);
}

__global__ void rs_kernel(const int* __restrict__ deg, float* __restrict__ rs, int count) {
    int i = blockIdx.x * blockDim.x + threadIdx.x;
    if (i < count) {
        int d = deg[i];
        rs[i] = rsqrtf((float)(d < 1 ? 1 : d));
    }
}

// ---------------- CSR build: 2-level exclusive scan + bucket fill --------------
__global__ void chunk_sum_kernel(const int* __restrict__ deg, int* __restrict__ csum, int n) {
    __shared__ int s[256];
    int i = blockIdx.x * 256 + threadIdx.x;
    s[threadIdx.x] = (i < n) ? deg[i] : 0;
    __syncthreads();
    #pragma unroll
    for (int st = 128; st > 0; st >>= 1) {
        if (threadIdx.x < st) s[threadIdx.x] += s[threadIdx.x + st];
        __syncthreads();
    }
    if (threadIdx.x == 0) csum[blockIdx.x] = s[0];
}

__global__ void scan_chunks_kernel(int* __restrict__ csum, int nc) {
    __shared__ int s[512];
    int t = threadIdx.x;
    int v0 = (t < nc) ? csum[t] : 0;
    s[t] = v0;
    __syncthreads();
    #pragma unroll
    for (int off = 1; off < 512; off <<= 1) {
        int v = (t >= off) ? s[t - off] : 0;
        __syncthreads();
        s[t] += v;
        __syncthreads();
    }
    if (t < nc) csum[t] = s[t] - v0;   // exclusive
}

__global__ void write_offsets_kernel(const int* __restrict__ deg, const int* __restrict__ csum,
                                     int* __restrict__ off, int* __restrict__ cur, int n) {
    __shared__ int s[256];
    int t = threadIdx.x;
    int i = blockIdx.x * 256 + t;
    int d = (i < n) ? deg[i] : 0;
    s[t] = d;
    __syncthreads();
    #pragma unroll
    for (int o = 1; o < 256; o <<= 1) {
        int v = (t >= o) ? s[t - o] : 0;
        __syncthreads();
        s[t] += v;
        __syncthreads();
    }
    int excl = s[t] - d + csum[blockIdx.x];
    if (i < n) {
        off[i] = excl;
        cur[i] = excl;
        if (i == n - 1) off[n] = excl + d;
    }
}

__global__ void csr_fill_kernel(const int* __restrict__ src, const int* __restrict__ dst,
                                const float* __restrict__ rs_out,
                                int* __restrict__ cur, int2* __restrict__ csr, int e) {
    int i = blockIdx.x * blockDim.x + threadIdx.x;
    if (i >= e) return;
    int s = src[i];
    float c = __ldg(rs_out + s);
    int slot = atomicAdd(cur + dst[i], 1);
    csr[slot] = make_int2(s, __float_as_int(c));
}

// ---------------- gather aggregation: agg[d] = rs_in[d] * sum_e rs_out[s] h[s] --
// one warp per dst node, lane handles 4 floats (float4), 4 edges in flight
__global__ void gather_kernel(const float* __restrict__ h,
                              const int2* __restrict__ csr, const int* __restrict__ off,
                              const float* __restrict__ rs_in,
                              float* __restrict__ agg, int n) {
    int w    = (blockIdx.x * blockDim.x + threadIdx.x) >> 5;
    int lane = threadIdx.x & 31;
    if (w >= n) return;
    int e0 = __ldg(off + w), e1 = __ldg(off + w + 1);
    float4 acc = make_float4(0.f, 0.f, 0.f, 0.f);
    int e = e0;
    for (; e + 3 < e1; e += 4) {
        int2 ea = __ldg(csr + e),     eb = __ldg(csr + e + 1);
        int2 ec = __ldg(csr + e + 2), ed = __ldg(csr + e + 3);
        float4 va = __ldg((const float4*)(h + (size_t)ea.x * HD) + lane);
        float4 vb = __ldg((const float4*)(h + (size_t)eb.x * HD) + lane);
        float4 vc = __ldg((const float4*)(h + (size_t)ec.x * HD) + lane);
        float4 vd = __ldg((const float4*)(h + (size_t)ed.x * HD) + lane);
        float ca = __int_as_float(ea.y), cb = __int_as_float(eb.y);
        float cc = __int_as_float(ec.y), cd = __int_as_float(ed.y);
        acc.x = fmaf(va.x, ca, acc.x); acc.y = fmaf(va.y, ca, acc.y);
        acc.z = fmaf(va.z, ca, acc.z); acc.w = fmaf(va.w, ca, acc.w);
        acc.x = fmaf(vb.x, cb, acc.x); acc.y = fmaf(vb.y, cb, acc.y);
        acc.z = fmaf(vb.z, cb, acc.z); acc.w = fmaf(vb.w, cb, acc.w);
        acc.x = fmaf(vc.x, cc, acc.x); acc.y = fmaf(vc.y, cc, acc.y);
        acc.z = fmaf(vc.z, cc, acc.z); acc.w = fmaf(vc.w, cc, acc.w);
        acc.x = fmaf(vd.x, cd, acc.x); acc.y = fmaf(vd.y, cd, acc.y);
        acc.z = fmaf(vd.z, cd, acc.z); acc.w = fmaf(vd.w, cd, acc.w);
    }
    for (; e < e1; e++) {
        int2 ea = __ldg(csr + e);
        float ca = __int_as_float(ea.y);
        float4 va = __ldg((const float4*)(h + (size_t)ea.x * HD) + lane);
        acc.x = fmaf(va.x, ca, acc.x); acc.y = fmaf(va.y, ca, acc.y);
        acc.z = fmaf(va.z, ca, acc.z); acc.w = fmaf(va.w, ca, acc.w);
    }
    float ri = __ldg(rs_in + w);
    acc.x *= ri; acc.y *= ri; acc.z *= ri; acc.w *= ri;
    ((float4*)(agg + (size_t)w * HD))[lane] = acc;
}

// ---------------- fused GEMM (f32x2, dup-A phase 1) ------------------------------
// out = BN(ReLU((sum_r agg_r @ Wg_r + bg) @ Wfc + bfc))
// Block tile 64 nodes x 128 outputs, 256 threads, thread = 4(m) x 8(n).
__global__ __launch_bounds__(256) void gemm_fused_kernel(
    const float* __restrict__ agg,     // [3][n][HD], already fully normalized
    const float* __restrict__ Wg,      // [3][HD][HD]
    const float* __restrict__ bg,      // [3][HD]
    const float* __restrict__ Wfc,     // [HD][HD]
    const float* __restrict__ bfc,     // [HD]
    const float* __restrict__ gamma, const float* __restrict__ beta,
    const float* __restrict__ mean,  const float* __restrict__ var,
    float* __restrict__ out, int n)
{
    extern __shared__ float smem[];
    float* Ws = smem;                  // 32*128 = 16 KB
    float* Tb = smem + 32 * HD;        // max(64*TBD, 64*TB2) = 64*132 floats = 33.8 KB

    const int tid = threadIdx.x;
    const int tn  = tid & 15;
    const int tm  = tid >> 4;
    const int jA  = tn * 4;
    const int jB  = 64 + tn * 4;
    const int m0  = tm * 4;
    const int bn0 = blockIdx.x * 64;

    const int lm = tid >> 2, kq = tid & 3;   // A loader: node lm, k-chunk kq*8
    const int kw = tid >> 3, jq = tid & 7;   // W loader: row kw, col-chunk jq*16
    const int gnode = bn0 + lm;

    ull acc[4][4];
    #pragma unroll
    for (int p = 0; p < 4; p++) {
        int j = (p < 2) ? (jA + p * 2) : (jB + (p - 2) * 2);
        float blo = __ldg(bg + j)     + __ldg(bg + HD + j)     + __ldg(bg + 2 * HD + j);
        float bhi = __ldg(bg + j + 1) + __ldg(bg + HD + j + 1) + __ldg(bg + 2 * HD + j + 1);
        ull b = pack2f(blo, bhi);
        #pragma unroll
        for (int i = 0; i < 4; i++) acc[i][p] = b;
    }

    // ---------------- phase 1: t = sum_r agg_r @ Wg_r + bg_sum ----------------
    // A staged DUPLICATED: Tb[m*TBD + 2k] = Tb[m*TBD + 2k+1] = A[m][k]
    for (int t = 0; t < 12; t++) {
        int r  = t >> 2;
        int kk = (t & 3) * 32;
        const float* Ar = agg + (size_t)r * n * HD;

        __syncthreads();
        float4 v0 = make_float4(0.f, 0.f, 0.f, 0.f), v1 = v0;
        if (gnode < n) {
            const float4* p = (const float4*)(Ar + (size_t)gnode * HD + kk + kq * 8);
            v0 = __ldg(p); v1 = __ldg(p + 1);
        }
        {
            float* as = &Tb[lm * TBD + kq * 16];
            *(float4*)(as)      = make_float4(v0.x, v0.x, v0.y, v0.y);
            *(float4*)(as + 4)  = make_float4(v0.z, v0.z, v0.w, v0.w);
            *(float4*)(as + 8)  = make_float4(v1.x, v1.x, v1.y, v1.y);
            *(float4*)(as + 12) = make_float4(v1.z, v1.z, v1.w, v1.w);
        }
        {
            const float4* wp = (const float4*)(Wg + ((size_t)r * HD + kk + kw) * HD + jq * 16);
            float4 w0 = __ldg(wp), w1 = __ldg(wp + 1), w2 = __ldg(wp + 2), w3 = __ldg(wp + 3);
            float* ws = &Ws[kw * HD + jq * 16];
            *(float4*)(ws)      = w0;
            *(float4*)(ws + 4)  = w1;
            *(float4*)(ws + 8)  = w2;
            *(float4*)(ws + 12) = w3;
        }
        __syncthreads();

        #pragma unroll
        for (int k2 = 0; k2 < 16; k2++) {      // two k per iteration
            ulonglong2 a0 = *(const ulonglong2*)&Tb[(m0 + 0) * TBD + k2 * 4];
            ulonglong2 a1 = *(const ulonglong2*)&Tb[(m0 + 1) * TBD + k2 * 4];
            ulonglong2 a2 = *(const ulonglong2*)&Tb[(m0 + 2) * TBD + k2 * 4];
            ulonglong2 a3 = *(const ulonglong2*)&Tb[(m0 + 3) * TBD + k2 * 4];
            ulonglong2 b0 = *(const ulonglong2*)&Ws[(2 * k2) * HD + jA];
            ulonglong2 b1 = *(const ulonglong2*)&Ws[(2 * k2) * HD + jB];
            fma2(acc[0][0], a0.x, b0.x); fma2(acc[0][1], a0.x, b0.y); fma2(acc[0][2], a0.x, b1.x); fma2(acc[0][3], a0.x, b1.y);
            fma2(acc[1][0], a1.x, b0.x); fma2(acc[1][1], a1.x, b0.y); fma2(acc[1][2], a1.x, b1.x); fma2(acc[1][3], a1.x, b1.y);
            fma2(acc[2][0], a2.x, b0.x); fma2(acc[2][1], a2.x, b0.y); fma2(acc[2][2], a2.x, b1.x); fma2(acc[2][3], a2.x, b1.y);
            fma2(acc[3][0], a3.x, b0.x); fma2(acc[3][1], a3.x, b0.y); fma2(acc[3][2], a3.x, b1.x); fma2(acc[3][3], a3.x, b1.y);
            ulonglong2 c0 = *(const ulonglong2*)&Ws[(2 * k2 + 1) * HD + jA];
            ulonglong2 c1 = *(const ulonglong2*)&Ws[(2 * k2 + 1) * HD + jB];
            fma2(acc[0][0], a0.y, c0.x); fma2(acc[0][1], a0.y, c0.y); fma2(acc[0][2], a0.y, c1.x); fma2(acc[0][3], a0.y, c1.y);
            fma2(acc[1][0], a1.y, c0.x); fma2(acc[1][1], a1.y, c0.y); fma2(acc[1][2], a1.y, c1.x); fma2(acc[1][3], a1.y, c1.y);
            fma2(acc[2][0], a2.y, c0.x); fma2(acc[2][1], a2.y, c0.y); fma2(acc[2][2], a2.y, c1.x); fma2(acc[2][3], a2.y, c1.y);
            fma2(acc[3][0], a3.y, c0.x); fma2(acc[3][1], a3.y, c0.y); fma2(acc[3][2], a3.y, c1.x); fma2(acc[3][3], a3.y, c1.y);
        }
    }

    // ---------------- write t into smem for second GEMM ----------------------
    __syncthreads();
    #pragma unroll
    for (int i = 0; i < 4; i++) {
        float2 u0 = unpack2(acc[i][0]), u1 = unpack2(acc[i][1]);
        float2 u2 = unpack2(acc[i][2]), u3 = unpack2(acc[i][3]);
        *(float4*)&Tb[(m0 + i) * TB2 + jA] = make_float4(u0.x, u0.y, u1.x, u1.y);
        *(float4*)&Tb[(m0 + i) * TB2 + jB] = make_float4(u2.x, u2.y, u3.x, u3.y);
    }

    ull acc2[4][4];
    #pragma unroll
    for (int p = 0; p < 4; p++) {
        int j = (p < 2) ? (jA + p * 2) : (jB + (p - 2) * 2);
        ull b = pack2f(__ldg(bfc + j), __ldg(bfc + j + 1));
        #pragma unroll
        for (int i = 0; i < 4; i++) acc2[i][p] = b;
    }

    // ---------------- phase 2: y = t @ Wfc + bfc ------------------------------
    for (int t = 0; t < 4; t++) {
        __syncthreads();
        {
            const float4* wp = (const float4*)(Wfc + ((size_t)t * 32 + kw) * HD + jq * 16);
            float4 w0 = __ldg(wp), w1 = __ldg(wp + 1), w2 = __ldg(wp + 2), w3 = __ldg(wp + 3);
            float* ws = &Ws[kw * HD + jq * 16];
            *(float4*)(ws)      = w0;
            *(float4*)(ws + 4)  = w1;
            *(float4*)(ws + 8)  = w2;
            *(float4*)(ws + 12) = w3;
        }
        __syncthreads();

        #pragma unroll
        for (int k = 0; k < 32; k++) {
            ull p0 = pack2(Tb[(m0 + 0) * TB2 + t * 32 + k]);
            ull p1 = pack2(Tb[(m0 + 1) * TB2 + t * 32 + k]);
            ull p2 = pack2(Tb[(m0 + 2) * TB2 + t * 32 + k]);
            ull p3 = pack2(Tb[(m0 + 3) * TB2 + t * 32 + k]);
            ulonglong2 b0 = *(const ulonglong2*)&Ws[k * HD + jA];
            ulonglong2 b1 = *(const ulonglong2*)&Ws[k * HD + jB];
            fma2(acc2[0][0], p0, b0.x); fma2(acc2[0][1], p0, b0.y); fma2(acc2[0][2], p0, b1.x); fma2(acc2[0][3], p0, b1.y);
            fma2(acc2[1][0], p1, b0.x); fma2(acc2[1][1], p1, b0.y); fma2(acc2[1][2], p1, b1.x); fma2(acc2[1][3], p1, b1.y);
            fma2(acc2[2][0], p2, b0.x); fma2(acc2[2][1], p2, b0.y); fma2(acc2[2][2], p2, b1.x); fma2(acc2[2][3], p2, b1.y);
            fma2(acc2[3][0], p3, b0.x); fma2(acc2[3][1], p3, b0.y); fma2(acc2[3][2], p3, b1.x); fma2(acc2[3][3], p3, b1.y);
        }
    }

    // ---------------- epilogue: ReLU + BatchNorm(eval) ------------------------
    float res[4][8];
    #pragma unroll
    for (int p = 0; p < 4; p++) {
        int j = (p < 2) ? (jA + p * 2) : (jB + (p - 2) * 2);
        float sc0 = __ldg(gamma + j)     * rsqrtf(__ldg(var + j)     + EPS);
        float sc1 = __ldg(gamma + j + 1) * rsqrtf(__ldg(var + j + 1) + EPS);
        float sh0 = __ldg(beta + j)     - __ldg(mean + j)     * sc0;
        float sh1 = __ldg(beta + j + 1) - __ldg(mean + j + 1) * sc1;
        #pragma unroll
        for (int i = 0; i < 4; i++) {
            float2 u = unpack2(acc2[i][p]);
            res[i][p * 2]     = fmaxf(u.x, 0.f) * sc0 + sh0;
            res[i][p * 2 + 1] = fmaxf(u.y, 0.f) * sc1 + sh1;
        }
    }
    #pragma unroll
    for (int i = 0; i < 4; i++) {
        int node = bn0 + m0 + i;
        if (node < n) {
            float* op = out + (size_t)node * HD;
            *(float4*)(op + jA) = make_float4(res[i][0], res[i][1], res[i][2], res[i][3]);
            *(float4*)(op + jB) = make_float4(res[i][4], res[i][5], res[i][6], res[i][7]);
        }
    }
}

// ---------------- launch --------------------------------------------------------
extern "C" void kernel_launch(void* const* d_in, const int* in_sizes, int n_in,
                              void* d_out, int out_size)
{
    const float* x     = (const float*)d_in[0];
    const int* srcs[3] = {(const int*)d_in[1], (const int*)d_in[3], (const int*)d_in[5]};
    const int* dsts[3] = {(const int*)d_in[2], (const int*)d_in[4], (const int*)d_in[6]};
    const float* Wgl[2] = {(const float*)d_in[7], (const float*)d_in[9]};
    const float* bgl[2] = {(const float*)d_in[8], (const float*)d_in[10]};
    const float* Wfc   = (const float*)d_in[11];
    const float* bfc   = (const float*)d_in[12];
    const float* gamma = (const float*)d_in[13];
    const float* beta  = (const float*)d_in[14];
    const float* mean  = (const float*)d_in[15];
    const float* var   = (const float*)d_in[16];

    int n = in_sizes[0] / HD;
    int es[3] = {in_sizes[1], in_sizes[3], in_sizes[5]};

    int *p_deg, *p_off, *p_cur, *p_csum;
    int2* p_csr;
    float *p_rs, *p_agg, *p_h;
    cudaGetSymbolAddress((void**)&p_deg,  g_deg);
    cudaGetSymbolAddress((void**)&p_rs,   g_rs);
    cudaGetSymbolAddress((void**)&p_off,  g_off);
    cudaGetSymbolAddress((void**)&p_cur,  g_cur);
    cudaGetSymbolAddress((void**)&p_csum, g_csum);
    cudaGetSymbolAddress((void**)&p_csr,  g_csr);
    cudaGetSymbolAddress((void**)&p_agg,  g_agg);
    cudaGetSymbolAddress((void**)&p_h,    g_h);

    const int NT = 256;
    const int nchunks = (n + 255) / 256;
    const int SMEM_BYTES = (32 * HD + 64 * TB2) * 4;   // 16KB + 33.8KB = 49.9KB

    cudaFuncSetAttribute(gemm_fused_kernel, cudaFuncAttributeMaxDynamicSharedMemorySize, SMEM_BYTES);

    // 1) degrees -> rsqrt normalizers
    zero_int_kernel<<<(6 * n + NT - 1) / NT, NT>>>(p_deg, 6 * n);
    for (int r = 0; r < 3; r++)
        count_pair_kernel<<<(es[r] + NT - 1) / NT, NT>>>(
            srcs[r], dsts[r], p_deg + (size_t)2 * r * n, p_deg + (size_t)(2 * r + 1) * n, es[r]);
    rs_kernel<<<(6 * n + NT - 1) / NT, NT>>>(p_deg, p_rs, 6 * n);

    // 2) CSR by dst (entries carry rs_out[src]); reused by both layers
    for (int r = 0; r < 3; r++) {
        const int* deg_in = p_deg + (size_t)(2 * r + 1) * n;
        int* off  = p_off  + (size_t)r * (NMAX + 1);
        int* cur  = p_cur  + (size_t)r * NMAX;
        int* csum = p_csum + (size_t)r * 512;
        int2* csr = p_csr  + (size_t)r * EMAX;
        chunk_sum_kernel<<<nchunks, 256>>>(deg_in, csum, n);
        scan_chunks_kernel<<<1, 512>>>(csum, nchunks);
        write_offsets_kernel<<<nchunks, 256>>>(deg_in, csum, off, cur, n);
        csr_fill_kernel<<<(es[r] + NT - 1) / NT, NT>>>(
            srcs[r], dsts[r], p_rs + (size_t)2 * r * n, cur, csr, es[r]);
    }

    // 3) layers: gather per relation, then fused GEMM
    const float* hin = x;
    for (int layer = 0; layer < 2; layer++) {
        for (int r = 0; r < 3; r++) {
            long long thr = (long long)n * 32;
            int blocks = (int)((thr + NT - 1) / NT);
            gather_kernel<<<blocks, NT>>>(hin,
                                          p_csr + (size_t)r * EMAX,
                                          p_off + (size_t)r * (NMAX + 1),
                                          p_rs + (size_t)(2 * r + 1) * n,  // rs_in
                                          p_agg + (size_t)r * n * HD, n);
        }
        float* outp = (layer == 0) ? p_h : (float*)d_out;
        gemm_fused_kernel<<<(n + 63) / 64, 256, SMEM_BYTES>>>(
            p_agg,
            Wgl[layer], bgl[layer],
            Wfc + (size_t)layer * HD * HD, bfc + (size_t)layer * HD,
            gamma + (size_t)layer * HD, beta + (size_t)layer * HD,
            mean + (size_t)layer * HD, var + (size_t)layer * HD,
            outp, n);
        hin = p_h;
    }
}

// round 6
// speedup vs baseline: 2.0325x; 1.6166x over previous
#include <cuda_runtime.h>
#include <cuda_bf16.h>
#include <cstdint>

#define HD   128
#define NMAX 100000
#define EMAX 1700000
#define EPS  1e-5f

typedef unsigned long long ull;
typedef __nv_bfloat16 bf16;

// ---------------- scratch (__device__ globals; no runtime allocation) ----------
__device__ int   g_deg [6 * NMAX];
__device__ float g_rs  [6 * NMAX];
__device__ int   g_off [3 * (NMAX + 1)];
__device__ int   g_cur [3 * NMAX];
__device__ int   g_csum[3 * 512];
__device__ int2  g_csr [3 * (size_t)EMAX];              // (src, bits(rs_out[src]))
__device__ bf16  g_ah  [(size_t)3 * NMAX * HD];         // agg hi (bf16)
__device__ bf16  g_al  [(size_t)3 * NMAX * HD];         // agg lo (bf16)
__device__ bf16  g_wt  [2 * 4 * 2 * HD * HD];           // [layer][slot0..3][hi/lo][k][n]
__device__ float g_h   [(size_t)NMAX * HD];             // layer-0 output

// ---------------- mma.sync / ldmatrix helpers (portable sm_80+ PTX) -------------
__device__ __forceinline__ uint32_t smem_to_u32(const void* p) {
    uint32_t a;
    asm("{ .reg .u64 t; cvta.to.shared.u64 t, %1; cvt.u32.u64 %0, t; }" : "=r"(a) : "l"(p));
    return a;
}
__device__ __forceinline__ void ldsm_x4(uint32_t r[4], uint32_t addr) {
    asm volatile("ldmatrix.sync.aligned.m8n8.x4.shared.b16 {%0,%1,%2,%3}, [%4];"
                 : "=r"(r[0]), "=r"(r[1]), "=r"(r[2]), "=r"(r[3]) : "r"(addr));
}
__device__ __forceinline__ void ldsm_x4t(uint32_t r[4], uint32_t addr) {
    asm volatile("ldmatrix.sync.aligned.m8n8.x4.trans.shared.b16 {%0,%1,%2,%3}, [%4];"
                 : "=r"(r[0]), "=r"(r[1]), "=r"(r[2]), "=r"(r[3]) : "r"(addr));
}
__device__ __forceinline__ void mma_bf16(float c[4], const uint32_t a[4], uint32_t b0, uint32_t b1) {
    asm volatile("mma.sync.aligned.m16n8k16.row.col.f32.bf16.bf16.f32 "
                 "{%0,%1,%2,%3}, {%4,%5,%6,%7}, {%8,%9}, {%0,%1,%2,%3};"
                 : "+f"(c[0]), "+f"(c[1]), "+f"(c[2]), "+f"(c[3])
                 : "r"(a[0]), "r"(a[1]), "r"(a[2]), "r"(a[3]), "r"(b0), "r"(b1));
}

// ---------------- small utility kernels ---------------------------------------
__global__ void zero_int_kernel(int* __restrict__ p, int count) {
    int i = blockIdx.x * blockDim.x + threadIdx.x;
    if (i < count) p[i] = 0;
}

__global__ void count_pair_kernel(const int* __restrict__ src, const int* __restrict__ dst,
                                  int* __restrict__ dout, int* __restrict__ din, int e) {
    int i = blockIdx.x * blockDim.x + threadIdx.x;
    if (i >= e) return;
    atomicAdd(dout + src[i], 1);
    atomicAdd(din  + dst[i], 1);
}

__global__ void rs_kernel(const int* __restrict__ deg, float* __restrict__ rs, int count) {
    int i = blockIdx.x * blockDim.x + threadIdx.x;
    if (i < count) {
        int d = deg[i];
        rs[i] = rsqrtf((float)(d < 1 ? 1 : d));
    }
}

// ---------------- CSR build ----------------------------------------------------
__global__ void chunk_sum_kernel(const int* __restrict__ deg, int* __restrict__ csum, int n) {
    __shared__ int s[256];
    int i = blockIdx.x * 256 + threadIdx.x;
    s[threadIdx.x] = (i < n) ? deg[i] : 0;
    __syncthreads();
    #pragma unroll
    for (int st = 128; st > 0; st >>= 1) {
        if (threadIdx.x < st) s[threadIdx.x] += s[threadIdx.x + st];
        __syncthreads();
    }
    if (threadIdx.x == 0) csum[blockIdx.x] = s[0];
}

__global__ void scan_chunks_kernel(int* __restrict__ csum, int nc) {
    __shared__ int s[512];
    int t = threadIdx.x;
    int v0 = (t < nc) ? csum[t] : 0;
    s[t] = v0;
    __syncthreads();
    #pragma unroll
    for (int off = 1; off < 512; off <<= 1) {
        int v = (t >= off) ? s[t - off] : 0;
        __syncthreads();
        s[t] += v;
        __syncthreads();
    }
    if (t < nc) csum[t] = s[t] - v0;
}

__global__ void write_offsets_kernel(const int* __restrict__ deg, const int* __restrict__ csum,
                                     int* __restrict__ off, int* __restrict__ cur, int n) {
    __shared__ int s[256];
    int t = threadIdx.x;
    int i = blockIdx.x * 256 + t;
    int d = (i < n) ? deg[i] : 0;
    s[t] = d;
    __syncthreads();
    #pragma unroll
    for (int o = 1; o < 256; o <<= 1) {
        int v = (t >= o) ? s[t - o] : 0;
        __syncthreads();
        s[t] += v;
        __syncthreads();
    }
    int excl = s[t] - d + csum[blockIdx.x];
    if (i < n) {
        off[i] = excl;
        cur[i] = excl;
        if (i == n - 1) off[n] = excl + d;
    }
}

__global__ void csr_fill_kernel(const int* __restrict__ src, const int* __restrict__ dst,
                                const float* __restrict__ rs_out,
                                int* __restrict__ cur, int2* __restrict__ csr, int e) {
    int i = blockIdx.x * blockDim.x + threadIdx.x;
    if (i >= e) return;
    int s = src[i];
    float c = __ldg(rs_out + s);
    int slot = atomicAdd(cur + dst[i], 1);
    csr[slot] = make_int2(s, __float_as_int(c));
}

// ---------------- gather: agg[d] = rs_in[d] * sum rs_out[s] h[s]; emits bf16 hi/lo
__global__ void gather_kernel(const float* __restrict__ h,
                              const int2* __restrict__ csr, const int* __restrict__ off,
                              const float* __restrict__ rs_in,
                              bf16* __restrict__ ah, bf16* __restrict__ al, int n) {
    int w    = (blockIdx.x * blockDim.x + threadIdx.x) >> 5;
    int lane = threadIdx.x & 31;
    if (w >= n) return;
    int e0 = __ldg(off + w), e1 = __ldg(off + w + 1);
    float4 acc = make_float4(0.f, 0.f, 0.f, 0.f);
    int e = e0;
    for (; e + 1 < e1; e += 2) {
        int2 ea = __ldg(csr + e), eb = __ldg(csr + e + 1);
        float ca = __int_as_float(ea.y), cb = __int_as_float(eb.y);
        float4 va = __ldg((const float4*)(h + (size_t)ea.x * HD) + lane);
        float4 vb = __ldg((const float4*)(h + (size_t)eb.x * HD) + lane);
        acc.x = fmaf(va.x, ca, acc.x); acc.y = fmaf(va.y, ca, acc.y);
        acc.z = fmaf(va.z, ca, acc.z); acc.w = fmaf(va.w, ca, acc.w);
        acc.x = fmaf(vb.x, cb, acc.x); acc.y = fmaf(vb.y, cb, acc.y);
        acc.z = fmaf(vb.z, cb, acc.z); acc.w = fmaf(vb.w, cb, acc.w);
    }
    if (e < e1) {
        int2 ea = __ldg(csr + e);
        float ca = __int_as_float(ea.y);
        float4 va = __ldg((const float4*)(h + (size_t)ea.x * HD) + lane);
        acc.x = fmaf(va.x, ca, acc.x); acc.y = fmaf(va.y, ca, acc.y);
        acc.z = fmaf(va.z, ca, acc.z); acc.w = fmaf(va.w, ca, acc.w);
    }
    float ri = __ldg(rs_in + w);
    acc.x *= ri; acc.y *= ri; acc.z *= ri; acc.w *= ri;

    bf16 h0 = __float2bfloat16(acc.x), h1 = __float2bfloat16(acc.y);
    bf16 h2 = __float2bfloat16(acc.z), h3 = __float2bfloat16(acc.w);
    bf16 l0 = __float2bfloat16(acc.x - __bfloat162float(h0));
    bf16 l1 = __float2bfloat16(acc.y - __bfloat162float(h1));
    bf16 l2 = __float2bfloat16(acc.z - __bfloat162float(h2));
    bf16 l3 = __float2bfloat16(acc.w - __bfloat162float(h3));
    __nv_bfloat162 hp0, hp1, lp0, lp1;
    hp0.x = h0; hp0.y = h1; hp1.x = h2; hp1.y = h3;
    lp0.x = l0; lp0.y = l1; lp1.x = l2; lp1.y = l3;
    uint2 hv = make_uint2(*(uint32_t*)&hp0, *(uint32_t*)&hp1);
    uint2 lv = make_uint2(*(uint32_t*)&lp0, *(uint32_t*)&lp1);
    ((uint2*)(ah + (size_t)w * HD))[lane] = hv;
    ((uint2*)(al + (size_t)w * HD))[lane] = lv;
}

// ---------------- weight prep: bf16 hi/lo split, layout [layer][slot][hi/lo][k][n]
__global__ void prep_weights_kernel(const float* __restrict__ Wg0, const float* __restrict__ Wg1,
                                    const float* __restrict__ Wfc, bf16* __restrict__ wt) {
    int idx = blockIdx.x * 256 + threadIdx.x;      // 2*4*16384
    if (idx >= 2 * 4 * 16384) return;
    int kn = idx & 16383;
    int slot = (idx >> 14) & 3;
    int layer = idx >> 16;
    float v;
    if (slot < 3) v = (layer ? Wg1 : Wg0)[(size_t)slot * 16384 + kn];
    else          v = Wfc[(size_t)layer * 16384 + kn];
    bf16 h = __float2bfloat16(v);
    bf16 l = __float2bfloat16(v - __bfloat162float(h));
    size_t base = (size_t)(layer * 4 + slot) * 2 * 16384 + kn;
    wt[base] = h;
    wt[base + 16384] = l;
}

// ---------------- fused mma.sync layer kernel ------------------------------------
// Block = 128 nodes x 128 outputs, 256 threads (8 warps, 4m x 2n, warp tile 32x64).
// Phase 1: 3 relations x 4 k32-chunks (A from agg hi/lo, B from Wg hi/lo).
// Transition: t + bg -> bf16 hi/lo in smem tbuf.
// Phase 2: 4 k32-chunks against Wfc. Epilogue ReLU + BN.

#define SA_STR 40      // phase-1 A row stride (bf16): 128x40
#define SB_STR 136     // B row stride (bf16): 32x136
#define TB_STR 136     // tbuf row stride (bf16): 128x136

#define OFF_BGS  0                                  // 128 f32
#define OFF_BFC  512
#define OFF_SC   1024
#define OFF_SH   1536
#define OFF_SB   2048                               // B hi (8704) + B lo (8704)
#define OFF_SBLO (OFF_SB + 32 * SB_STR * 2)
#define OFF_TBUF (OFF_SBLO + 32 * SB_STR * 2)       // t hi (34816) + t lo (34816)
#define OFF_TLO  (OFF_TBUF + 128 * TB_STR * 2)
#define OFF_SA   OFF_TBUF                           // phase-1 A hi overlays tbuf
#define OFF_SALO (OFF_SA + 128 * SA_STR * 2)
#define SMEM_TOT (OFF_TLO + 128 * TB_STR * 2)

__global__ __launch_bounds__(256) void mma_layer_kernel(
    const bf16* __restrict__ ah,       // [3n][HD]
    const bf16* __restrict__ al,
    const bf16* __restrict__ wt,       // this layer: [4 slots][2][128][128]
    const float* __restrict__ bg,      // [3][HD]
    const float* __restrict__ bfc,
    const float* __restrict__ gamma, const float* __restrict__ beta,
    const float* __restrict__ mean,  const float* __restrict__ var,
    float* __restrict__ out, int n)
{
    extern __shared__ char smem[];
    const uint32_t sb = smem_to_u32(smem);
    float* bgs  = (float*)(smem + OFF_BGS);
    float* bfcs = (float*)(smem + OFF_BFC);
    float* scs  = (float*)(smem + OFF_SC);
    float* shs  = (float*)(smem + OFF_SH);

    const int tid  = threadIdx.x;
    const int lane = tid & 31;
    const int wid  = tid >> 5;
    const int wm   = wid & 3;          // warp row  (m: 32 each)
    const int wn   = wid >> 2;         // warp col  (n: 64 each)
    const int bn0  = blockIdx.x * 128;

    if (tid < HD) {
        bgs[tid]  = __ldg(bg + tid) + __ldg(bg + HD + tid) + __ldg(bg + 2 * HD + tid);
        bfcs[tid] = __ldg(bfc + tid);
        float sc = __ldg(gamma + tid) * rsqrtf(__ldg(var + tid) + EPS);
        scs[tid] = sc;
        shs[tid] = __ldg(beta + tid) - __ldg(mean + tid) * sc;
    }

    // ldmatrix source addresses (byte offsets in smem space)
    const int lrow = lane & 15, lcol = lane >> 4;
    // A (phase1): row = wm*32 + mi*16 + lrow, koff = kb + lcol*8, stride SA_STR
    // B:          row = kb + lrow, col = wn*64 + g*16 + lcol*8,   stride SB_STR
    // A (phase2): same as phase1 but stride TB_STR, base OFF_TBUF/OFF_TLO

    float acc[2][8][4];
    #pragma unroll
    for (int mi = 0; mi < 2; mi++)
        #pragma unroll
        for (int t = 0; t < 8; t++)
            #pragma unroll
            for (int q = 0; q < 4; q++) acc[mi][t][q] = 0.f;

    // staging index maps
    const int ar = tid >> 1, ahalf = tid & 1;        // A: 128 rows x 2 halves of 16
    const int br = tid >> 3, bc = tid & 7;           // B: 32 rows x 8 chunks of 16

    // ================= phase 1: 3 relations, K=128 each =======================
    for (int r = 0; r < 3; r++) {
        const bf16* ah_base = ah + (size_t)r * n * HD;
        const bf16* al_base = al + (size_t)r * n * HD;
        const bf16* wh = wt + (size_t)(r * 2)     * 16384;
        const bf16* wl = wt + (size_t)(r * 2 + 1) * 16384;
        for (int kc = 0; kc < 4; kc++) {
            __syncthreads();
            // stage A hi/lo [128][32]
            {
                int gnode = bn0 + ar;
                uint4 v0 = {0,0,0,0}, v1 = {0,0,0,0}, u0 = {0,0,0,0}, u1 = {0,0,0,0};
                if (gnode < n) {
                    const uint4* ph = (const uint4*)(ah_base + (size_t)gnode * HD + kc * 32 + ahalf * 16);
                    const uint4* pl = (const uint4*)(al_base + (size_t)gnode * HD + kc * 32 + ahalf * 16);
                    v0 = __ldg(ph); v1 = __ldg(ph + 1);
                    u0 = __ldg(pl); u1 = __ldg(pl + 1);
                }
                bf16* dh = (bf16*)(smem + OFF_SA)   + ar * SA_STR + ahalf * 16;
                bf16* dl = (bf16*)(smem + OFF_SALO) + ar * SA_STR + ahalf * 16;
                *(uint4*)dh = v0; *(uint4*)(dh + 8) = v1;
                *(uint4*)dl = u0; *(uint4*)(dl + 8) = u1;
            }
            // stage B hi/lo [32][128]
            {
                const uint4* ph = (const uint4*)(wh + (size_t)(kc * 32 + br) * HD + bc * 16);
                const uint4* pl = (const uint4*)(wl + (size_t)(kc * 32 + br) * HD + bc * 16);
                uint4 v0 = __ldg(ph), v1 = __ldg(ph + 1);
                uint4 u0 = __ldg(pl), u1 = __ldg(pl + 1);
                bf16* dh = (bf16*)(smem + OFF_SB)   + br * SB_STR + bc * 16;
                bf16* dl = (bf16*)(smem + OFF_SBLO) + br * SB_STR + bc * 16;
                *(uint4*)dh = v0; *(uint4*)(dh + 8) = v1;
                *(uint4*)dl = u0; *(uint4*)(dl + 8) = u1;
            }
            __syncthreads();

            #pragma unroll
            for (int kb = 0; kb < 32; kb += 16) {
                uint32_t ahf[2][4], alf[2][4];
                #pragma unroll
                for (int mi = 0; mi < 2; mi++) {
                    uint32_t aoff = (uint32_t)((wm * 32 + mi * 16 + lrow) * SA_STR + kb + lcol * 8) * 2;
                    ldsm_x4(ahf[mi], sb + OFF_SA   + aoff);
                    ldsm_x4(alf[mi], sb + OFF_SALO + aoff);
                }
                #pragma unroll
                for (int g = 0; g < 4; g++) {
                    uint32_t bh[4], bl[4];
                    uint32_t boff = (uint32_t)((kb + lrow) * SB_STR + wn * 64 + g * 16 + lcol * 8) * 2;
                    ldsm_x4t(bh, sb + OFF_SB   + boff);
                    ldsm_x4t(bl, sb + OFF_SBLO + boff);
                    #pragma unroll
                    for (int mi = 0; mi < 2; mi++) {
                        #pragma unroll
                        for (int nj = 0; nj < 2; nj++) {
                            mma_bf16(acc[mi][g * 2 + nj], ahf[mi], bh[nj * 2], bh[nj * 2 + 1]);
                            mma_bf16(acc[mi][g * 2 + nj], ahf[mi], bl[nj * 2], bl[nj * 2 + 1]);
                            mma_bf16(acc[mi][g * 2 + nj], alf[mi], bh[nj * 2], bh[nj * 2 + 1]);
                        }
                    }
                }
            }
        }
    }

    // ================= transition: t = acc + bg -> tbuf hi/lo ===================
    __syncthreads();
    {
        bf16* th = (bf16*)(smem + OFF_TBUF);
        bf16* tl = (bf16*)(smem + OFF_TLO);
        #pragma unroll
        for (int mi = 0; mi < 2; mi++) {
            #pragma unroll
            for (int t = 0; t < 8; t++) {
                int g = t >> 1, nj = t & 1;
                int row0 = wm * 32 + mi * 16 + (lane >> 2);
                int col  = wn * 64 + g * 16 + nj * 8 + (lane & 3) * 2;
                float b0 = bgs[col], b1 = bgs[col + 1];
                #pragma unroll
                for (int half = 0; half < 2; half++) {
                    int row = row0 + half * 8;
                    float t0 = acc[mi][t][half * 2]     + b0;
                    float t1 = acc[mi][t][half * 2 + 1] + b1;
                    bf16 h0 = __float2bfloat16(t0), h1 = __float2bfloat16(t1);
                    bf16 l0 = __float2bfloat16(t0 - __bfloat162float(h0));
                    bf16 l1 = __float2bfloat16(t1 - __bfloat162float(h1));
                    __nv_bfloat162 hp, lp;
                    hp.x = h0; hp.y = h1; lp.x = l0; lp.y = l1;
                    *(uint32_t*)(th + row * TB_STR + col) = *(uint32_t*)&hp;
                    *(uint32_t*)(tl + row * TB_STR + col) = *(uint32_t*)&lp;
                }
                #pragma unroll
                for (int q = 0; q < 4; q++) acc[mi][t][q] = 0.f;
            }
        }
    }

    // ================= phase 2: y = t @ Wfc =====================================
    {
        const bf16* wh = wt + (size_t)(3 * 2)     * 16384;
        const bf16* wl = wt + (size_t)(3 * 2 + 1) * 16384;
        for (int kc = 0; kc < 4; kc++) {
            __syncthreads();
            {
                const uint4* ph = (const uint4*)(wh + (size_t)(kc * 32 + br) * HD + bc * 16);
                const uint4* pl = (const uint4*)(wl + (size_t)(kc * 32 + br) * HD + bc * 16);
                uint4 v0 = __ldg(ph), v1 = __ldg(ph + 1);
                uint4 u0 = __ldg(pl), u1 = __ldg(pl + 1);
                bf16* dh = (bf16*)(smem + OFF_SB)   + br * SB_STR + bc * 16;
                bf16* dl = (bf16*)(smem + OFF_SBLO) + br * SB_STR + bc * 16;
                *(uint4*)dh = v0; *(uint4*)(dh + 8) = v1;
                *(uint4*)dl = u0; *(uint4*)(dl + 8) = u1;
            }
            __syncthreads();

            #pragma unroll
            for (int kb2 = 0; kb2 < 32; kb2 += 16) {
                int kb = kc * 32 + kb2;
                uint32_t ahf[2][4], alf[2][4];
                #pragma unroll
                for (int mi = 0; mi < 2; mi++) {
                    uint32_t aoff = (uint32_t)((wm * 32 + mi * 16 + lrow) * TB_STR + kb + lcol * 8) * 2;
                    ldsm_x4(ahf[mi], sb + OFF_TBUF + aoff);
                    ldsm_x4(alf[mi], sb + OFF_TLO  + aoff);
                }
                #pragma unroll
                for (int g = 0; g < 4; g++) {
                    uint32_t bh[4], bl[4];
                    uint32_t boff = (uint32_t)((kb2 + lrow) * SB_STR + wn * 64 + g * 16 + lcol * 8) * 2;
                    ldsm_x4t(bh, sb + OFF_SB   + boff);
                    ldsm_x4t(bl, sb + OFF_SBLO + boff);
                    #pragma unroll
                    for (int mi = 0; mi < 2; mi++) {
                        #pragma unroll
                        for (int nj = 0; nj < 2; nj++) {
                            mma_bf16(acc[mi][g * 2 + nj], ahf[mi], bh[nj * 2], bh[nj * 2 + 1]);
                            mma_bf16(acc[mi][g * 2 + nj], ahf[mi], bl[nj * 2], bl[nj * 2 + 1]);
                            mma_bf16(acc[mi][g * 2 + nj], alf[mi], bh[nj * 2], bh[nj * 2 + 1]);
                        }
                    }
                }
            }
        }
    }

    // ================= epilogue: ReLU + BN, store ==============================
    #pragma unroll
    for (int mi = 0; mi < 2; mi++) {
        #pragma unroll
        for (int t = 0; t < 8; t++) {
            int g = t >> 1, nj = t & 1;
            int row0 = wm * 32 + mi * 16 + (lane >> 2);
            int col  = wn * 64 + g * 16 + nj * 8 + (lane & 3) * 2;
            float bf0 = bfcs[col], bf1 = bfcs[col + 1];
            float sc0 = scs[col], sc1 = scs[col + 1];
            float sh0 = shs[col], sh1 = shs[col + 1];
            #pragma unroll
            for (int half = 0; half < 2; half++) {
                int node = bn0 + row0 + half * 8;
                if (node < n) {
                    float y0 = fmaxf(acc[mi][t][half * 2]     + bf0, 0.f);
                    float y1 = fmaxf(acc[mi][t][half * 2 + 1] + bf1, 0.f);
                    float2 v = make_float2(y0 * sc0 + sh0, y1 * sc1 + sh1);
                    *(float2*)(out + (size_t)node * HD + col) = v;
                }
            }
        }
    }
}

// ---------------- launch --------------------------------------------------------
extern "C" void kernel_launch(void* const* d_in, const int* in_sizes, int n_in,
                              void* d_out, int out_size)
{
    const float* x     = (const float*)d_in[0];
    const int* srcs[3] = {(const int*)d_in[1], (const int*)d_in[3], (const int*)d_in[5]};
    const int* dsts[3] = {(const int*)d_in[2], (const int*)d_in[4], (const int*)d_in[6]};
    const float* Wg0   = (const float*)d_in[7];
    const float* bg0   = (const float*)d_in[8];
    const float* Wg1   = (const float*)d_in[9];
    const float* bg1   = (const float*)d_in[10];
    const float* Wfc   = (const float*)d_in[11];
    const float* bfc   = (const float*)d_in[12];
    const float* gamma = (const float*)d_in[13];
    const float* beta  = (const float*)d_in[14];
    const float* mean  = (const float*)d_in[15];
    const float* var   = (const float*)d_in[16];

    int n = in_sizes[0] / HD;
    int es[3] = {in_sizes[1], in_sizes[3], in_sizes[5]};

    int *p_deg, *p_off, *p_cur, *p_csum;
    int2* p_csr;
    float *p_rs, *p_h;
    bf16 *p_ah, *p_al, *p_wt;
    cudaGetSymbolAddress((void**)&p_deg,  g_deg);
    cudaGetSymbolAddress((void**)&p_rs,   g_rs);
    cudaGetSymbolAddress((void**)&p_off,  g_off);
    cudaGetSymbolAddress((void**)&p_cur,  g_cur);
    cudaGetSymbolAddress((void**)&p_csum, g_csum);
    cudaGetSymbolAddress((void**)&p_csr,  g_csr);
    cudaGetSymbolAddress((void**)&p_ah,   g_ah);
    cudaGetSymbolAddress((void**)&p_al,   g_al);
    cudaGetSymbolAddress((void**)&p_wt,   g_wt);
    cudaGetSymbolAddress((void**)&p_h,    g_h);

    const int NT = 256;
    const int nchunks = (n + 255) / 256;

    cudaFuncSetAttribute(mma_layer_kernel, cudaFuncAttributeMaxDynamicSharedMemorySize, SMEM_TOT);

    // 1) degrees -> rsqrt normalizers
    zero_int_kernel<<<(6 * n + NT - 1) / NT, NT>>>(p_deg, 6 * n);
    for (int r = 0; r < 3; r++)
        count_pair_kernel<<<(es[r] + NT - 1) / NT, NT>>>(
            srcs[r], dsts[r], p_deg + (size_t)2 * r * n, p_deg + (size_t)(2 * r + 1) * n, es[r]);
    rs_kernel<<<(6 * n + NT - 1) / NT, NT>>>(p_deg, p_rs, 6 * n);

    // weight prep (tiny)
    prep_weights_kernel<<<512, 256>>>(Wg0, Wg1, Wfc, p_wt);

    // 2) CSR by dst (entries carry rs_out[src]); reused by both layers
    for (int r = 0; r < 3; r++) {
        const int* deg_in = p_deg + (size_t)(2 * r + 1) * n;
        int* off  = p_off  + (size_t)r * (NMAX + 1);
        int* cur  = p_cur  + (size_t)r * NMAX;
        int* csum = p_csum + (size_t)r * 512;
        int2* csr = p_csr  + (size_t)r * EMAX;
        chunk_sum_kernel<<<nchunks, 256>>>(deg_in, csum, n);
        scan_chunks_kernel<<<1, 512>>>(csum, nchunks);
        write_offsets_kernel<<<nchunks, 256>>>(deg_in, csum, off, cur, n);
        csr_fill_kernel<<<(es[r] + NT - 1) / NT, NT>>>(
            srcs[r], dsts[r], p_rs + (size_t)2 * r * n, cur, csr, es[r]);
    }

    // 3) layers
    const float* hin = x;
    int mblocks = (n + 127) / 128;
    for (int layer = 0; layer < 2; layer++) {
        for (int r = 0; r < 3; r++) {
            long long thr = (long long)n * 32;
            int blocks = (int)((thr + NT - 1) / NT);
            gather_kernel<<<blocks, NT>>>(hin,
                                          p_csr + (size_t)r * EMAX,
                                          p_off + (size_t)r * (NMAX + 1),
                                          p_rs + (size_t)(2 * r + 1) * n,
                                          p_ah + (size_t)r * n * HD,
                                          p_al + (size_t)r * n * HD, n);
        }
        float* outp = (layer == 0) ? p_h : (float*)d_out;
        mma_layer_kernel<<<mblocks, 256, SMEM_TOT>>>(
            p_ah, p_al,
            p_wt + (size_t)layer * 4 * 2 * 16384,
            (layer == 0) ? bg0 : bg1,
            bfc + (size_t)layer * HD,
            gamma + (size_t)layer * HD, beta + (size_t)layer * HD,
            mean + (size_t)layer * HD, var + (size_t)layer * HD,
            outp, n);
        hin = p_h;
    }
}

// round 7
// speedup vs baseline: 2.1372x; 1.0515x over previous
#include <cuda_runtime.h>
#include <cuda_bf16.h>
#include <cuda_fp16.h>
#include <cstdint>

#define HD   128
#define NMAX 100000
#define EMAX 1700000
#define EPS  1e-5f

typedef unsigned long long ull;
typedef __nv_bfloat16 bf16;

// ---------------- scratch (__device__ globals; no runtime allocation) ----------
__device__ int    g_deg [6 * NMAX];
__device__ float  g_rs  [6 * NMAX];
__device__ int    g_off [3 * (NMAX + 1)];
__device__ int    g_cur [3 * NMAX];
__device__ int    g_csum[3 * 512];
__device__ int2   g_csr [3 * (size_t)EMAX];             // (src, bits(rs_out[src]))
__device__ bf16   g_ah  [(size_t)3 * NMAX * HD];        // agg hi (bf16)
__device__ bf16   g_al  [(size_t)3 * NMAX * HD];        // agg lo (bf16)
__device__ bf16   g_wt  [2 * 4 * 2 * HD * HD];          // [layer][slot0..3][hi/lo][k][n]
__device__ __half g_xh  [(size_t)NMAX * HD];            // fp16 copy of x
__device__ __half g_h   [(size_t)NMAX * HD];            // layer-0 output (fp16)

// ---------------- mma.sync / ldmatrix helpers (portable sm_80+ PTX) -------------
__device__ __forceinline__ uint32_t smem_to_u32(const void* p) {
    uint32_t a;
    asm("{ .reg .u64 t; cvta.to.shared.u64 t, %1; cvt.u32.u64 %0, t; }" : "=r"(a) : "l"(p));
    return a;
}
__device__ __forceinline__ void ldsm_x4(uint32_t r[4], uint32_t addr) {
    asm volatile("ldmatrix.sync.aligned.m8n8.x4.shared.b16 {%0,%1,%2,%3}, [%4];"
                 : "=r"(r[0]), "=r"(r[1]), "=r"(r[2]), "=r"(r[3]) : "r"(addr));
}
__device__ __forceinline__ void ldsm_x4t(uint32_t r[4], uint32_t addr) {
    asm volatile("ldmatrix.sync.aligned.m8n8.x4.trans.shared.b16 {%0,%1,%2,%3}, [%4];"
                 : "=r"(r[0]), "=r"(r[1]), "=r"(r[2]), "=r"(r[3]) : "r"(addr));
}
__device__ __forceinline__ void mma_bf16(float c[4], const uint32_t a[4], uint32_t b0, uint32_t b1) {
    asm volatile("mma.sync.aligned.m16n8k16.row.col.f32.bf16.bf16.f32 "
                 "{%0,%1,%2,%3}, {%4,%5,%6,%7}, {%8,%9}, {%0,%1,%2,%3};"
                 : "+f"(c[0]), "+f"(c[1]), "+f"(c[2]), "+f"(c[3])
                 : "r"(a[0]), "r"(a[1]), "r"(a[2]), "r"(a[3]), "r"(b0), "r"(b1));
}

// ---------------- small utility kernels ---------------------------------------
__global__ void zero_int_kernel(int* __restrict__ p, int count) {
    int i = blockIdx.x * blockDim.x + threadIdx.x;
    if (i < count) p[i] = 0;
}

__global__ void x2h_kernel(const float* __restrict__ x, __half* __restrict__ xh, int count4) {
    int i = blockIdx.x * blockDim.x + threadIdx.x;
    if (i >= count4) return;
    float4 v = __ldg((const float4*)x + i);
    __half2 p0 = __floats2half2_rn(v.x, v.y);
    __half2 p1 = __floats2half2_rn(v.z, v.w);
    uint2 o = make_uint2(*(uint32_t*)&p0, *(uint32_t*)&p1);
    ((uint2*)xh)[i] = o;
}

__global__ void count_pair_kernel(const int* __restrict__ src, const int* __restrict__ dst,
                                  int* __restrict__ dout, int* __restrict__ din, int e) {
    int i = blockIdx.x * blockDim.x + threadIdx.x;
    if (i >= e) return;
    atomicAdd(dout + src[i], 1);
    atomicAdd(din  + dst[i], 1);
}

__global__ void rs_kernel(const int* __restrict__ deg, float* __restrict__ rs, int count) {
    int i = blockIdx.x * blockDim.x + threadIdx.x;
    if (i < count) {
        int d = deg[i];
        rs[i] = rsqrtf((float)(d < 1 ? 1 : d));
    }
}

// ---------------- CSR build ----------------------------------------------------
__global__ void chunk_sum_kernel(const int* __restrict__ deg, int* __restrict__ csum, int n) {
    __shared__ int s[256];
    int i = blockIdx.x * 256 + threadIdx.x;
    s[threadIdx.x] = (i < n) ? deg[i] : 0;
    __syncthreads();
    #pragma unroll
    for (int st = 128; st > 0; st >>= 1) {
        if (threadIdx.x < st) s[threadIdx.x] += s[threadIdx.x + st];
        __syncthreads();
    }
    if (threadIdx.x == 0) csum[blockIdx.x] = s[0];
}

__global__ void scan_chunks_kernel(int* __restrict__ csum, int nc) {
    __shared__ int s[512];
    int t = threadIdx.x;
    int v0 = (t < nc) ? csum[t] : 0;
    s[t] = v0;
    __syncthreads();
    #pragma unroll
    for (int off = 1; off < 512; off <<= 1) {
        int v = (t >= off) ? s[t - off] : 0;
        __syncthreads();
        s[t] += v;
        __syncthreads();
    }
    if (t < nc) csum[t] = s[t] - v0;
}

__global__ void write_offsets_kernel(const int* __restrict__ deg, const int* __restrict__ csum,
                                     int* __restrict__ off, int* __restrict__ cur, int n) {
    __shared__ int s[256];
    int t = threadIdx.x;
    int i = blockIdx.x * 256 + t;
    int d = (i < n) ? deg[i] : 0;
    s[t] = d;
    __syncthreads();
    #pragma unroll
    for (int o = 1; o < 256; o <<= 1) {
        int v = (t >= o) ? s[t - o] : 0;
        __syncthreads();
        s[t] += v;
        __syncthreads();
    }
    int excl = s[t] - d + csum[blockIdx.x];
    if (i < n) {
        off[i] = excl;
        cur[i] = excl;
        if (i == n - 1) off[n] = excl + d;
    }
}

__global__ void csr_fill_kernel(const int* __restrict__ src, const int* __restrict__ dst,
                                const float* __restrict__ rs_out,
                                int* __restrict__ cur, int2* __restrict__ csr, int e) {
    int i = blockIdx.x * blockDim.x + threadIdx.x;
    if (i >= e) return;
    int s = src[i];
    float c = __ldg(rs_out + s);
    int slot = atomicAdd(cur + dst[i], 1);
    csr[slot] = make_int2(s, __float_as_int(c));
}

// ---------------- gather: agg[d] = rs_in[d] * sum rs_out[s] h[s]; fp16 in, bf16 hi/lo out
__global__ void gather_kernel(const __half* __restrict__ h,
                              const int2* __restrict__ csr, const int* __restrict__ off,
                              const float* __restrict__ rs_in,
                              bf16* __restrict__ ah, bf16* __restrict__ al, int n) {
    int w    = (blockIdx.x * blockDim.x + threadIdx.x) >> 5;
    int lane = threadIdx.x & 31;
    if (w >= n) return;
    int e0 = __ldg(off + w), e1 = __ldg(off + w + 1);
    float4 acc = make_float4(0.f, 0.f, 0.f, 0.f);
    int e = e0;
    for (; e + 1 < e1; e += 2) {
        int2 ea = __ldg(csr + e), eb = __ldg(csr + e + 1);
        float ca = __int_as_float(ea.y), cb = __int_as_float(eb.y);
        uint2 ra = __ldg((const uint2*)(h + (size_t)ea.x * HD) + lane);
        uint2 rb = __ldg((const uint2*)(h + (size_t)eb.x * HD) + lane);
        float2 a0 = __half22float2(*(__half2*)&ra.x), a1 = __half22float2(*(__half2*)&ra.y);
        float2 b0 = __half22float2(*(__half2*)&rb.x), b1 = __half22float2(*(__half2*)&rb.y);
        acc.x = fmaf(a0.x, ca, acc.x); acc.y = fmaf(a0.y, ca, acc.y);
        acc.z = fmaf(a1.x, ca, acc.z); acc.w = fmaf(a1.y, ca, acc.w);
        acc.x = fmaf(b0.x, cb, acc.x); acc.y = fmaf(b0.y, cb, acc.y);
        acc.z = fmaf(b1.x, cb, acc.z); acc.w = fmaf(b1.y, cb, acc.w);
    }
    if (e < e1) {
        int2 ea = __ldg(csr + e);
        float ca = __int_as_float(ea.y);
        uint2 ra = __ldg((const uint2*)(h + (size_t)ea.x * HD) + lane);
        float2 a0 = __half22float2(*(__half2*)&ra.x), a1 = __half22float2(*(__half2*)&ra.y);
        acc.x = fmaf(a0.x, ca, acc.x); acc.y = fmaf(a0.y, ca, acc.y);
        acc.z = fmaf(a1.x, ca, acc.z); acc.w = fmaf(a1.y, ca, acc.w);
    }
    float ri = __ldg(rs_in + w);
    acc.x *= ri; acc.y *= ri; acc.z *= ri; acc.w *= ri;

    bf16 h0 = __float2bfloat16(acc.x), h1 = __float2bfloat16(acc.y);
    bf16 h2 = __float2bfloat16(acc.z), h3 = __float2bfloat16(acc.w);
    bf16 l0 = __float2bfloat16(acc.x - __bfloat162float(h0));
    bf16 l1 = __float2bfloat16(acc.y - __bfloat162float(h1));
    bf16 l2 = __float2bfloat16(acc.z - __bfloat162float(h2));
    bf16 l3 = __float2bfloat16(acc.w - __bfloat162float(h3));
    __nv_bfloat162 hp0, hp1, lp0, lp1;
    hp0.x = h0; hp0.y = h1; hp1.x = h2; hp1.y = h3;
    lp0.x = l0; lp0.y = l1; lp1.x = l2; lp1.y = l3;
    uint2 hv = make_uint2(*(uint32_t*)&hp0, *(uint32_t*)&hp1);
    uint2 lv = make_uint2(*(uint32_t*)&lp0, *(uint32_t*)&lp1);
    ((uint2*)(ah + (size_t)w * HD))[lane] = hv;
    ((uint2*)(al + (size_t)w * HD))[lane] = lv;
}

// ---------------- weight prep: bf16 hi/lo split, layout [layer][slot][hi/lo][k][n]
__global__ void prep_weights_kernel(const float* __restrict__ Wg0, const float* __restrict__ Wg1,
                                    const float* __restrict__ Wfc, bf16* __restrict__ wt) {
    int idx = blockIdx.x * 256 + threadIdx.x;      // 2*4*16384
    if (idx >= 2 * 4 * 16384) return;
    int kn = idx & 16383;
    int slot = (idx >> 14) & 3;
    int layer = idx >> 16;
    float v;
    if (slot < 3) v = (layer ? Wg1 : Wg0)[(size_t)slot * 16384 + kn];
    else          v = Wfc[(size_t)layer * 16384 + kn];
    bf16 h = __float2bfloat16(v);
    bf16 l = __float2bfloat16(v - __bfloat162float(h));
    size_t base = (size_t)(layer * 4 + slot) * 2 * 16384 + kn;
    wt[base] = h;
    wt[base + 16384] = l;
}

// ---------------- fused mma.sync layer kernel ------------------------------------
// Block = 128 nodes x 128 outputs, 256 threads (8 warps, 4m x 2n, warp tile 32x64).

#define SA_STR 40      // phase-1 A row stride (bf16): 128x40
#define SB_STR 136     // B row stride (bf16): 32x136
#define TB_STR 136     // tbuf row stride (bf16): 128x136

#define OFF_BGS  0                                  // 128 f32
#define OFF_BFC  512
#define OFF_SC   1024
#define OFF_SH   1536
#define OFF_SB   2048                               // B hi (8704) + B lo (8704)
#define OFF_SBLO (OFF_SB + 32 * SB_STR * 2)
#define OFF_TBUF (OFF_SBLO + 32 * SB_STR * 2)       // t hi (34816) + t lo (34816)
#define OFF_TLO  (OFF_TBUF + 128 * TB_STR * 2)
#define OFF_SA   OFF_TBUF                           // phase-1 A hi overlays tbuf
#define OFF_SALO (OFF_SA + 128 * SA_STR * 2)
#define SMEM_TOT (OFF_TLO + 128 * TB_STR * 2)

__global__ __launch_bounds__(256) void mma_layer_kernel(
    const bf16* __restrict__ ah,       // [3n][HD]
    const bf16* __restrict__ al,
    const bf16* __restrict__ wt,       // this layer: [4 slots][2][128][128]
    const float* __restrict__ bg,      // [3][HD]
    const float* __restrict__ bfc,
    const float* __restrict__ gamma, const float* __restrict__ beta,
    const float* __restrict__ mean,  const float* __restrict__ var,
    float* __restrict__ outf,          // fp32 output (layer 1) or null
    __half* __restrict__ outh,         // fp16 output (layer 0) or null
    int n)
{
    extern __shared__ char smem[];
    const uint32_t sb = smem_to_u32(smem);
    float* bgs  = (float*)(smem + OFF_BGS);
    float* bfcs = (float*)(smem + OFF_BFC);
    float* scs  = (float*)(smem + OFF_SC);
    float* shs  = (float*)(smem + OFF_SH);

    const int tid  = threadIdx.x;
    const int lane = tid & 31;
    const int wid  = tid >> 5;
    const int wm   = wid & 3;          // warp row  (m: 32 each)
    const int wn   = wid >> 2;         // warp col  (n: 64 each)
    const int bn0  = blockIdx.x * 128;

    if (tid < HD) {
        bgs[tid]  = __ldg(bg + tid) + __ldg(bg + HD + tid) + __ldg(bg + 2 * HD + tid);
        bfcs[tid] = __ldg(bfc + tid);
        float sc = __ldg(gamma + tid) * rsqrtf(__ldg(var + tid) + EPS);
        scs[tid] = sc;
        shs[tid] = __ldg(beta + tid) - __ldg(mean + tid) * sc;
    }

    const int lrow = lane & 15, lcol = lane >> 4;

    float acc[2][8][4];
    #pragma unroll
    for (int mi = 0; mi < 2; mi++)
        #pragma unroll
        for (int t = 0; t < 8; t++)
            #pragma unroll
            for (int q = 0; q < 4; q++) acc[mi][t][q] = 0.f;

    const int ar = tid >> 1, ahalf = tid & 1;        // A: 128 rows x 2 halves of 16
    const int br = tid >> 3, bc = tid & 7;           // B: 32 rows x 8 chunks of 16

    // ================= phase 1: 3 relations, K=128 each =======================
    for (int r = 0; r < 3; r++) {
        const bf16* ah_base = ah + (size_t)r * n * HD;
        const bf16* al_base = al + (size_t)r * n * HD;
        const bf16* wh = wt + (size_t)(r * 2)     * 16384;
        const bf16* wl = wt + (size_t)(r * 2 + 1) * 16384;
        for (int kc = 0; kc < 4; kc++) {
            __syncthreads();
            {
                int gnode = bn0 + ar;
                uint4 v0 = {0,0,0,0}, v1 = {0,0,0,0}, u0 = {0,0,0,0}, u1 = {0,0,0,0};
                if (gnode < n) {
                    const uint4* ph = (const uint4*)(ah_base + (size_t)gnode * HD + kc * 32 + ahalf * 16);
                    const uint4* pl = (const uint4*)(al_base + (size_t)gnode * HD + kc * 32 + ahalf * 16);
                    v0 = __ldg(ph); v1 = __ldg(ph + 1);
                    u0 = __ldg(pl); u1 = __ldg(pl + 1);
                }
                bf16* dh = (bf16*)(smem + OFF_SA)   + ar * SA_STR + ahalf * 16;
                bf16* dl = (bf16*)(smem + OFF_SALO) + ar * SA_STR + ahalf * 16;
                *(uint4*)dh = v0; *(uint4*)(dh + 8) = v1;
                *(uint4*)dl = u0; *(uint4*)(dl + 8) = u1;
            }
            {
                const uint4* ph = (const uint4*)(wh + (size_t)(kc * 32 + br) * HD + bc * 16);
                const uint4* pl = (const uint4*)(wl + (size_t)(kc * 32 + br) * HD + bc * 16);
                uint4 v0 = __ldg(ph), v1 = __ldg(ph + 1);
                uint4 u0 = __ldg(pl), u1 = __ldg(pl + 1);
                bf16* dh = (bf16*)(smem + OFF_SB)   + br * SB_STR + bc * 16;
                bf16* dl = (bf16*)(smem + OFF_SBLO) + br * SB_STR + bc * 16;
                *(uint4*)dh = v0; *(uint4*)(dh + 8) = v1;
                *(uint4*)dl = u0; *(uint4*)(dl + 8) = u1;
            }
            __syncthreads();

            #pragma unroll
            for (int kb = 0; kb < 32; kb += 16) {
                uint32_t ahf[2][4], alf[2][4];
                #pragma unroll
                for (int mi = 0; mi < 2; mi++) {
                    uint32_t aoff = (uint32_t)((wm * 32 + mi * 16 + lrow) * SA_STR + kb + lcol * 8) * 2;
                    ldsm_x4(ahf[mi], sb + OFF_SA   + aoff);
                    ldsm_x4(alf[mi], sb + OFF_SALO + aoff);
                }
                #pragma unroll
                for (int g = 0; g < 4; g++) {
                    uint32_t bh[4], bl[4];
                    uint32_t boff = (uint32_t)((kb + lrow) * SB_STR + wn * 64 + g * 16 + lcol * 8) * 2;
                    ldsm_x4t(bh, sb + OFF_SB   + boff);
                    ldsm_x4t(bl, sb + OFF_SBLO + boff);
                    #pragma unroll
                    for (int mi = 0; mi < 2; mi++) {
                        #pragma unroll
                        for (int nj = 0; nj < 2; nj++) {
                            mma_bf16(acc[mi][g * 2 + nj], ahf[mi], bh[nj * 2], bh[nj * 2 + 1]);
                            mma_bf16(acc[mi][g * 2 + nj], ahf[mi], bl[nj * 2], bl[nj * 2 + 1]);
                            mma_bf16(acc[mi][g * 2 + nj], alf[mi], bh[nj * 2], bh[nj * 2 + 1]);
                        }
                    }
                }
            }
        }
    }

    // ================= transition: t = acc + bg -> tbuf hi/lo ===================
    __syncthreads();
    {
        bf16* th = (bf16*)(smem + OFF_TBUF);
        bf16* tl = (bf16*)(smem + OFF_TLO);
        #pragma unroll
        for (int mi = 0; mi < 2; mi++) {
            #pragma unroll
            for (int t = 0; t < 8; t++) {
                int g = t >> 1, nj = t & 1;
                int row0 = wm * 32 + mi * 16 + (lane >> 2);
                int col  = wn * 64 + g * 16 + nj * 8 + (lane & 3) * 2;
                float b0 = bgs[col], b1 = bgs[col + 1];
                #pragma unroll
                for (int half = 0; half < 2; half++) {
                    int row = row0 + half * 8;
                    float t0 = acc[mi][t][half * 2]     + b0;
                    float t1 = acc[mi][t][half * 2 + 1] + b1;
                    bf16 h0 = __float2bfloat16(t0), h1 = __float2bfloat16(t1);
                    bf16 l0 = __float2bfloat16(t0 - __bfloat162float(h0));
                    bf16 l1 = __float2bfloat16(t1 - __bfloat162float(h1));
                    __nv_bfloat162 hp, lp;
                    hp.x = h0; hp.y = h1; lp.x = l0; lp.y = l1;
                    *(uint32_t*)(th + row * TB_STR + col) = *(uint32_t*)&hp;
                    *(uint32_t*)(tl + row * TB_STR + col) = *(uint32_t*)&lp;
                }
                #pragma unroll
                for (int q = 0; q < 4; q++) acc[mi][t][q] = 0.f;
            }
        }
    }

    // ================= phase 2: y = t @ Wfc =====================================
    {
        const bf16* wh = wt + (size_t)(3 * 2)     * 16384;
        const bf16* wl = wt + (size_t)(3 * 2 + 1) * 16384;
        for (int kc = 0; kc < 4; kc++) {
            __syncthreads();
            {
                const uint4* ph = (const uint4*)(wh + (size_t)(kc * 32 + br) * HD + bc * 16);
                const uint4* pl = (const uint4*)(wl + (size_t)(kc * 32 + br) * HD + bc * 16);
                uint4 v0 = __ldg(ph), v1 = __ldg(ph + 1);
                uint4 u0 = __ldg(pl), u1 = __ldg(pl + 1);
                bf16* dh = (bf16*)(smem + OFF_SB)   + br * SB_STR + bc * 16;
                bf16* dl = (bf16*)(smem + OFF_SBLO) + br * SB_STR + bc * 16;
                *(uint4*)dh = v0; *(uint4*)(dh + 8) = v1;
                *(uint4*)dl = u0; *(uint4*)(dl + 8) = u1;
            }
            __syncthreads();

            #pragma unroll
            for (int kb2 = 0; kb2 < 32; kb2 += 16) {
                int kb = kc * 32 + kb2;
                uint32_t ahf[2][4], alf[2][4];
                #pragma unroll
                for (int mi = 0; mi < 2; mi++) {
                    uint32_t aoff = (uint32_t)((wm * 32 + mi * 16 + lrow) * TB_STR + kb + lcol * 8) * 2;
                    ldsm_x4(ahf[mi], sb + OFF_TBUF + aoff);
                    ldsm_x4(alf[mi], sb + OFF_TLO  + aoff);
                }
                #pragma unroll
                for (int g = 0; g < 4; g++) {
                    uint32_t bh[4], bl[4];
                    uint32_t boff = (uint32_t)((kb2 + lrow) * SB_STR + wn * 64 + g * 16 + lcol * 8) * 2;
                    ldsm_x4t(bh, sb + OFF_SB   + boff);
                    ldsm_x4t(bl, sb + OFF_SBLO + boff);
                    #pragma unroll
                    for (int mi = 0; mi < 2; mi++) {
                        #pragma unroll
                        for (int nj = 0; nj < 2; nj++) {
                            mma_bf16(acc[mi][g * 2 + nj], ahf[mi], bh[nj * 2], bh[nj * 2 + 1]);
                            mma_bf16(acc[mi][g * 2 + nj], ahf[mi], bl[nj * 2], bl[nj * 2 + 1]);
                            mma_bf16(acc[mi][g * 2 + nj], alf[mi], bh[nj * 2], bh[nj * 2 + 1]);
                        }
                    }
                }
            }
        }
    }

    // ================= epilogue: ReLU + BN, store ==============================
    #pragma unroll
    for (int mi = 0; mi < 2; mi++) {
        #pragma unroll
        for (int t = 0; t < 8; t++) {
            int g = t >> 1, nj = t & 1;
            int row0 = wm * 32 + mi * 16 + (lane >> 2);
            int col  = wn * 64 + g * 16 + nj * 8 + (lane & 3) * 2;
            float bf0 = bfcs[col], bf1 = bfcs[col + 1];
            float sc0 = scs[col], sc1 = scs[col + 1];
            float sh0 = shs[col], sh1 = shs[col + 1];
            #pragma unroll
            for (int half = 0; half < 2; half++) {
                int node = bn0 + row0 + half * 8;
                if (node < n) {
                    float y0 = fmaxf(acc[mi][t][half * 2]     + bf0, 0.f);
                    float y1 = fmaxf(acc[mi][t][half * 2 + 1] + bf1, 0.f);
                    float v0 = y0 * sc0 + sh0;
                    float v1 = y1 * sc1 + sh1;
                    if (outh) {
                        __half2 hv = __floats2half2_rn(v0, v1);
                        *(uint32_t*)(outh + (size_t)node * HD + col) = *(uint32_t*)&hv;
                    } else {
                        *(float2*)(outf + (size_t)node * HD + col) = make_float2(v0, v1);
                    }
                }
            }
        }
    }
}

// ---------------- launch --------------------------------------------------------
extern "C" void kernel_launch(void* const* d_in, const int* in_sizes, int n_in,
                              void* d_out, int out_size)
{
    const float* x     = (const float*)d_in[0];
    const int* srcs[3] = {(const int*)d_in[1], (const int*)d_in[3], (const int*)d_in[5]};
    const int* dsts[3] = {(const int*)d_in[2], (const int*)d_in[4], (const int*)d_in[6]};
    const float* Wg0   = (const float*)d_in[7];
    const float* bg0   = (const float*)d_in[8];
    const float* Wg1   = (const float*)d_in[9];
    const float* bg1   = (const float*)d_in[10];
    const float* Wfc   = (const float*)d_in[11];
    const float* bfc   = (const float*)d_in[12];
    const float* gamma = (const float*)d_in[13];
    const float* beta  = (const float*)d_in[14];
    const float* mean  = (const float*)d_in[15];
    const float* var   = (const float*)d_in[16];

    int n = in_sizes[0] / HD;
    int es[3] = {in_sizes[1], in_sizes[3], in_sizes[5]};

    int *p_deg, *p_off, *p_cur, *p_csum;
    int2* p_csr;
    float *p_rs;
    bf16 *p_ah, *p_al, *p_wt;
    __half *p_xh, *p_h;
    cudaGetSymbolAddress((void**)&p_deg,  g_deg);
    cudaGetSymbolAddress((void**)&p_rs,   g_rs);
    cudaGetSymbolAddress((void**)&p_off,  g_off);
    cudaGetSymbolAddress((void**)&p_cur,  g_cur);
    cudaGetSymbolAddress((void**)&p_csum, g_csum);
    cudaGetSymbolAddress((void**)&p_csr,  g_csr);
    cudaGetSymbolAddress((void**)&p_ah,   g_ah);
    cudaGetSymbolAddress((void**)&p_al,   g_al);
    cudaGetSymbolAddress((void**)&p_wt,   g_wt);
    cudaGetSymbolAddress((void**)&p_xh,   g_xh);
    cudaGetSymbolAddress((void**)&p_h,    g_h);

    const int NT = 256;
    const int nchunks = (n + 255) / 256;

    cudaFuncSetAttribute(mma_layer_kernel, cudaFuncAttributeMaxDynamicSharedMemorySize, SMEM_TOT);

    // 0) convert x to fp16
    int c4 = n * HD / 4;
    x2h_kernel<<<(c4 + NT - 1) / NT, NT>>>(x, p_xh, c4);

    // 1) degrees -> rsqrt normalizers
    zero_int_kernel<<<(6 * n + NT - 1) / NT, NT>>>(p_deg, 6 * n);
    for (int r = 0; r < 3; r++)
        count_pair_kernel<<<(es[r] + NT - 1) / NT, NT>>>(
            srcs[r], dsts[r], p_deg + (size_t)2 * r * n, p_deg + (size_t)(2 * r + 1) * n, es[r]);
    rs_kernel<<<(6 * n + NT - 1) / NT, NT>>>(p_deg, p_rs, 6 * n);

    // weight prep (tiny)
    prep_weights_kernel<<<512, 256>>>(Wg0, Wg1, Wfc, p_wt);

    // 2) CSR by dst (entries carry rs_out[src]); reused by both layers
    for (int r = 0; r < 3; r++) {
        const int* deg_in = p_deg + (size_t)(2 * r + 1) * n;
        int* off  = p_off  + (size_t)r * (NMAX + 1);
        int* cur  = p_cur  + (size_t)r * NMAX;
        int* csum = p_csum + (size_t)r * 512;
        int2* csr = p_csr  + (size_t)r * EMAX;
        chunk_sum_kernel<<<nchunks, 256>>>(deg_in, csum, n);
        scan_chunks_kernel<<<1, 512>>>(csum, nchunks);
        write_offsets_kernel<<<nchunks, 256>>>(deg_in, csum, off, cur, n);
        csr_fill_kernel<<<(es[r] + NT - 1) / NT, NT>>>(
            srcs[r], dsts[r], p_rs + (size_t)2 * r * n, cur, csr, es[r]);
    }

    // 3) layers
    int mblocks = (n + 127) / 128;
    for (int layer = 0; layer < 2; layer++) {
        const __half* hin = (layer == 0) ? p_xh : p_h;
        for (int r = 0; r < 3; r++) {
            long long thr = (long long)n * 32;
            int blocks = (int)((thr + NT - 1) / NT);
            gather_kernel<<<blocks, NT>>>(hin,
                                          p_csr + (size_t)r * EMAX,
                                          p_off + (size_t)r * (NMAX + 1),
                                          p_rs + (size_t)(2 * r + 1) * n,
                                          p_ah + (size_t)r * n * HD,
                                          p_al + (size_t)r * n * HD, n);
        }
        mma_layer_kernel<<<mblocks, 256, SMEM_TOT>>>(
            p_ah, p_al,
            p_wt + (size_t)layer * 4 * 2 * 16384,
            (layer == 0) ? bg0 : bg1,
            bfc + (size_t)layer * HD,
            gamma + (size_t)layer * HD, beta + (size_t)layer * HD,
            mean + (size_t)layer * HD, var + (size_t)layer * HD,
            (layer == 0) ? nullptr : (float*)d_out,
            (layer == 0) ? p_h : nullptr,
            n);
    }
}

// round 8
// speedup vs baseline: 3.1242x; 1.4618x over previous
#include <cuda_runtime.h>
#include <cuda_bf16.h>
#include <cuda_fp16.h>
#include <cstdint>

#define HD   128
#define NMAX 100000
#define EMAX 1700000
#define EPS  1e-5f

typedef unsigned long long ull;

// ---------------- scratch (__device__ globals; no runtime allocation) ----------
__device__ int    g_deg [6 * NMAX];
__device__ float  g_rs  [6 * NMAX];
__device__ int    g_off [3 * (NMAX + 1)];
__device__ int    g_cur [3 * NMAX];
__device__ int    g_csum[3 * 512];
__device__ int2   g_csr [3 * (size_t)EMAX];             // (src, bits(rs_out[src]))
__device__ __half g_af  [(size_t)3 * NMAX * HD];        // agg (fp16)
__device__ __half g_wt  [2 * 4 * HD * HD];              // [layer][slot0..3][k][n] fp16
__device__ __half g_xh  [(size_t)NMAX * HD];            // fp16 copy of x
__device__ __half g_h   [(size_t)NMAX * HD];            // layer-0 output (fp16)

// ---------------- mma.sync / ldmatrix helpers (portable sm_80+ PTX) -------------
__device__ __forceinline__ uint32_t smem_to_u32(const void* p) {
    uint32_t a;
    asm("{ .reg .u64 t; cvta.to.shared.u64 t, %1; cvt.u32.u64 %0, t; }" : "=r"(a) : "l"(p));
    return a;
}
__device__ __forceinline__ void ldsm_x4(uint32_t r[4], uint32_t addr) {
    asm volatile("ldmatrix.sync.aligned.m8n8.x4.shared.b16 {%0,%1,%2,%3}, [%4];"
                 : "=r"(r[0]), "=r"(r[1]), "=r"(r[2]), "=r"(r[3]) : "r"(addr));
}
__device__ __forceinline__ void ldsm_x4t(uint32_t r[4], uint32_t addr) {
    asm volatile("ldmatrix.sync.aligned.m8n8.x4.trans.shared.b16 {%0,%1,%2,%3}, [%4];"
                 : "=r"(r[0]), "=r"(r[1]), "=r"(r[2]), "=r"(r[3]) : "r"(addr));
}
__device__ __forceinline__ void mma_f16(float c[4], const uint32_t a[4], uint32_t b0, uint32_t b1) {
    asm volatile("mma.sync.aligned.m16n8k16.row.col.f32.f16.f16.f32 "
                 "{%0,%1,%2,%3}, {%4,%5,%6,%7}, {%8,%9}, {%0,%1,%2,%3};"
                 : "+f"(c[0]), "+f"(c[1]), "+f"(c[2]), "+f"(c[3])
                 : "r"(a[0]), "r"(a[1]), "r"(a[2]), "r"(a[3]), "r"(b0), "r"(b1));
}

// ---------------- small utility kernels ---------------------------------------
__global__ void zero_int_kernel(int* __restrict__ p, int count) {
    int i = blockIdx.x * blockDim.x + threadIdx.x;
    if (i < count) p[i] = 0;
}

__global__ void x2h_kernel(const float* __restrict__ x, __half* __restrict__ xh, int count4) {
    int i = blockIdx.x * blockDim.x + threadIdx.x;
    if (i >= count4) return;
    float4 v = __ldg((const float4*)x + i);
    __half2 p0 = __floats2half2_rn(v.x, v.y);
    __half2 p1 = __floats2half2_rn(v.z, v.w);
    uint2 o = make_uint2(*(uint32_t*)&p0, *(uint32_t*)&p1);
    ((uint2*)xh)[i] = o;
}

__global__ void count_pair_kernel(const int* __restrict__ src, const int* __restrict__ dst,
                                  int* __restrict__ dout, int* __restrict__ din, int e) {
    int i = blockIdx.x * blockDim.x + threadIdx.x;
    if (i >= e) return;
    atomicAdd(dout + src[i], 1);
    atomicAdd(din  + dst[i], 1);
}

__global__ void rs_kernel(const int* __restrict__ deg, float* __restrict__ rs, int count) {
    int i = blockIdx.x * blockDim.x + threadIdx.x;
    if (i < count) {
        int d = deg[i];
        rs[i] = rsqrtf((float)(d < 1 ? 1 : d));
    }
}

// ---------------- CSR build ----------------------------------------------------
__global__ void chunk_sum_kernel(const int* __restrict__ deg, int* __restrict__ csum, int n) {
    __shared__ int s[256];
    int i = blockIdx.x * 256 + threadIdx.x;
    s[threadIdx.x] = (i < n) ? deg[i] : 0;
    __syncthreads();
    #pragma unroll
    for (int st = 128; st > 0; st >>= 1) {
        if (threadIdx.x < st) s[threadIdx.x] += s[threadIdx.x + st];
        __syncthreads();
    }
    if (threadIdx.x == 0) csum[blockIdx.x] = s[0];
}

__global__ void scan_chunks_kernel(int* __restrict__ csum, int nc) {
    __shared__ int s[512];
    int t = threadIdx.x;
    int v0 = (t < nc) ? csum[t] : 0;
    s[t] = v0;
    __syncthreads();
    #pragma unroll
    for (int off = 1; off < 512; off <<= 1) {
        int v = (t >= off) ? s[t - off] : 0;
        __syncthreads();
        s[t] += v;
        __syncthreads();
    }
    if (t < nc) csum[t] = s[t] - v0;
}

__global__ void write_offsets_kernel(const int* __restrict__ deg, const int* __restrict__ csum,
                                     int* __restrict__ off, int* __restrict__ cur, int n) {
    __shared__ int s[256];
    int t = threadIdx.x;
    int i = blockIdx.x * 256 + t;
    int d = (i < n) ? deg[i] : 0;
    s[t] = d;
    __syncthreads();
    #pragma unroll
    for (int o = 1; o < 256; o <<= 1) {
        int v = (t >= o) ? s[t - o] : 0;
        __syncthreads();
        s[t] += v;
        __syncthreads();
    }
    int excl = s[t] - d + csum[blockIdx.x];
    if (i < n) {
        off[i] = excl;
        cur[i] = excl;
        if (i == n - 1) off[n] = excl + d;
    }
}

__global__ void csr_fill_kernel(const int* __restrict__ src, const int* __restrict__ dst,
                                const float* __restrict__ rs_out,
                                int* __restrict__ cur, int2* __restrict__ csr, int e) {
    int i = blockIdx.x * blockDim.x + threadIdx.x;
    if (i >= e) return;
    int s = src[i];
    float c = __ldg(rs_out + s);
    int slot = atomicAdd(cur + dst[i], 1);
    csr[slot] = make_int2(s, __float_as_int(c));
}

// ---------------- gather: agg[d] = rs_in[d] * sum rs_out[s] h[s]; fp16 in/out ---
__global__ void gather_kernel(const __half* __restrict__ h,
                              const int2* __restrict__ csr, const int* __restrict__ off,
                              const float* __restrict__ rs_in,
                              __half* __restrict__ af, int n) {
    int w    = (blockIdx.x * blockDim.x + threadIdx.x) >> 5;
    int lane = threadIdx.x & 31;
    if (w >= n) return;
    int e0 = __ldg(off + w), e1 = __ldg(off + w + 1);
    float4 acc = make_float4(0.f, 0.f, 0.f, 0.f);
    int e = e0;
    for (; e + 1 < e1; e += 2) {
        int2 ea = __ldg(csr + e), eb = __ldg(csr + e + 1);
        float ca = __int_as_float(ea.y), cb = __int_as_float(eb.y);
        uint2 ra = __ldg((const uint2*)(h + (size_t)ea.x * HD) + lane);
        uint2 rb = __ldg((const uint2*)(h + (size_t)eb.x * HD) + lane);
        float2 a0 = __half22float2(*(__half2*)&ra.x), a1 = __half22float2(*(__half2*)&ra.y);
        float2 b0 = __half22float2(*(__half2*)&rb.x), b1 = __half22float2(*(__half2*)&rb.y);
        acc.x = fmaf(a0.x, ca, acc.x); acc.y = fmaf(a0.y, ca, acc.y);
        acc.z = fmaf(a1.x, ca, acc.z); acc.w = fmaf(a1.y, ca, acc.w);
        acc.x = fmaf(b0.x, cb, acc.x); acc.y = fmaf(b0.y, cb, acc.y);
        acc.z = fmaf(b1.x, cb, acc.z); acc.w = fmaf(b1.y, cb, acc.w);
    }
    if (e < e1) {
        int2 ea = __ldg(csr + e);
        float ca = __int_as_float(ea.y);
        uint2 ra = __ldg((const uint2*)(h + (size_t)ea.x * HD) + lane);
        float2 a0 = __half22float2(*(__half2*)&ra.x), a1 = __half22float2(*(__half2*)&ra.y);
        acc.x = fmaf(a0.x, ca, acc.x); acc.y = fmaf(a0.y, ca, acc.y);
        acc.z = fmaf(a1.x, ca, acc.z); acc.w = fmaf(a1.y, ca, acc.w);
    }
    float ri = __ldg(rs_in + w);
    __half2 p0 = __floats2half2_rn(acc.x * ri, acc.y * ri);
    __half2 p1 = __floats2half2_rn(acc.z * ri, acc.w * ri);
    uint2 hv = make_uint2(*(uint32_t*)&p0, *(uint32_t*)&p1);
    ((uint2*)(af + (size_t)w * HD))[lane] = hv;
}

// ---------------- weight prep: fp16, layout [layer][slot][k][n] -----------------
__global__ void prep_weights_kernel(const float* __restrict__ Wg0, const float* __restrict__ Wg1,
                                    const float* __restrict__ Wfc, __half* __restrict__ wt) {
    int idx = blockIdx.x * 256 + threadIdx.x;      // 2*4*16384
    if (idx >= 2 * 4 * 16384) return;
    int kn = idx & 16383;
    int slot = (idx >> 14) & 3;
    int layer = idx >> 16;
    float v;
    if (slot < 3) v = (layer ? Wg1 : Wg0)[(size_t)slot * 16384 + kn];
    else          v = Wfc[(size_t)layer * 16384 + kn];
    wt[(size_t)(layer * 4 + slot) * 16384 + kn] = __float2half_rn(v);
}

// ---------------- fused mma.sync layer kernel (single-pass fp16) ----------------
// Block = 128 nodes x 128 outputs, 256 threads (8 warps, 4m x 2n, warp tile 32x64).

#define SA_STR 40      // phase-1 A row stride (fp16): 128x40
#define SB_STR 136     // B row stride (fp16): 32x136
#define TB_STR 136     // tbuf row stride (fp16): 128x136

#define OFF_BGS  0                                  // 128 f32
#define OFF_BFC  512
#define OFF_SC   1024
#define OFF_SH   1536
#define OFF_SB   2048                               // B (8704)
#define OFF_TBUF (OFF_SB + 32 * SB_STR * 2)         // t (34816); phase-1 A overlays
#define OFF_SA   OFF_TBUF
#define SMEM_TOT (OFF_TBUF + 128 * TB_STR * 2)      // 45568 B

__global__ __launch_bounds__(256) void mma_layer_kernel(
    const __half* __restrict__ af,     // [3n][HD]
    const __half* __restrict__ wt,     // this layer: [4 slots][128][128]
    const float* __restrict__ bg,      // [3][HD]
    const float* __restrict__ bfc,
    const float* __restrict__ gamma, const float* __restrict__ beta,
    const float* __restrict__ mean,  const float* __restrict__ var,
    float* __restrict__ outf,          // fp32 output (layer 1) or null
    __half* __restrict__ outh,         // fp16 output (layer 0) or null
    int n)
{
    extern __shared__ char smem[];
    const uint32_t sb = smem_to_u32(smem);
    float* bgs  = (float*)(smem + OFF_BGS);
    float* bfcs = (float*)(smem + OFF_BFC);
    float* scs  = (float*)(smem + OFF_SC);
    float* shs  = (float*)(smem + OFF_SH);

    const int tid  = threadIdx.x;
    const int lane = tid & 31;
    const int wid  = tid >> 5;
    const int wm   = wid & 3;          // warp row  (m: 32 each)
    const int wn   = wid >> 2;         // warp col  (n: 64 each)
    const int bn0  = blockIdx.x * 128;

    if (tid < HD) {
        bgs[tid]  = __ldg(bg + tid) + __ldg(bg + HD + tid) + __ldg(bg + 2 * HD + tid);
        bfcs[tid] = __ldg(bfc + tid);
        float sc = __ldg(gamma + tid) * rsqrtf(__ldg(var + tid) + EPS);
        scs[tid] = sc;
        shs[tid] = __ldg(beta + tid) - __ldg(mean + tid) * sc;
    }

    const int lrow = lane & 15, lcol = lane >> 4;

    float acc[2][8][4];
    #pragma unroll
    for (int mi = 0; mi < 2; mi++)
        #pragma unroll
        for (int t = 0; t < 8; t++)
            #pragma unroll
            for (int q = 0; q < 4; q++) acc[mi][t][q] = 0.f;

    const int ar = tid >> 1, ahalf = tid & 1;        // A: 128 rows x 2 halves of 16
    const int br = tid >> 3, bc = tid & 7;           // B: 32 rows x 8 chunks of 16

    // ================= phase 1: 3 relations, K=128 each =======================
    for (int r = 0; r < 3; r++) {
        const __half* af_base = af + (size_t)r * n * HD;
        const __half* wp_base = wt + (size_t)r * 16384;
        for (int kc = 0; kc < 4; kc++) {
            __syncthreads();
            // stage A [128][32]
            {
                int gnode = bn0 + ar;
                uint4 v0 = {0,0,0,0}, v1 = {0,0,0,0};
                if (gnode < n) {
                    const uint4* ph = (const uint4*)(af_base + (size_t)gnode * HD + kc * 32 + ahalf * 16);
                    v0 = __ldg(ph); v1 = __ldg(ph + 1);
                }
                __half* dh = (__half*)(smem + OFF_SA) + ar * SA_STR + ahalf * 16;
                *(uint4*)dh = v0; *(uint4*)(dh + 8) = v1;
            }
            // stage B [32][128]
            {
                const uint4* ph = (const uint4*)(wp_base + (size_t)(kc * 32 + br) * HD + bc * 16);
                uint4 v0 = __ldg(ph), v1 = __ldg(ph + 1);
                __half* dh = (__half*)(smem + OFF_SB) + br * SB_STR + bc * 16;
                *(uint4*)dh = v0; *(uint4*)(dh + 8) = v1;
            }
            __syncthreads();

            #pragma unroll
            for (int kb = 0; kb < 32; kb += 16) {
                uint32_t ahf[2][4];
                #pragma unroll
                for (int mi = 0; mi < 2; mi++) {
                    uint32_t aoff = (uint32_t)((wm * 32 + mi * 16 + lrow) * SA_STR + kb + lcol * 8) * 2;
                    ldsm_x4(ahf[mi], sb + OFF_SA + aoff);
                }
                #pragma unroll
                for (int g = 0; g < 4; g++) {
                    uint32_t bh[4];
                    uint32_t boff = (uint32_t)((kb + lrow) * SB_STR + wn * 64 + g * 16 + lcol * 8) * 2;
                    ldsm_x4t(bh, sb + OFF_SB + boff);
                    #pragma unroll
                    for (int mi = 0; mi < 2; mi++) {
                        #pragma unroll
                        for (int nj = 0; nj < 2; nj++)
                            mma_f16(acc[mi][g * 2 + nj], ahf[mi], bh[nj * 2], bh[nj * 2 + 1]);
                    }
                }
            }
        }
    }

    // ================= transition: t = acc + bg -> tbuf (fp16) =================
    __syncthreads();
    {
        __half* th = (__half*)(smem + OFF_TBUF);
        #pragma unroll
        for (int mi = 0; mi < 2; mi++) {
            #pragma unroll
            for (int t = 0; t < 8; t++) {
                int g = t >> 1, nj = t & 1;
                int row0 = wm * 32 + mi * 16 + (lane >> 2);
                int col  = wn * 64 + g * 16 + nj * 8 + (lane & 3) * 2;
                float b0 = bgs[col], b1 = bgs[col + 1];
                #pragma unroll
                for (int half = 0; half < 2; half++) {
                    int row = row0 + half * 8;
                    __half2 hp = __floats2half2_rn(acc[mi][t][half * 2] + b0,
                                                   acc[mi][t][half * 2 + 1] + b1);
                    *(uint32_t*)(th + row * TB_STR + col) = *(uint32_t*)&hp;
                }
                #pragma unroll
                for (int q = 0; q < 4; q++) acc[mi][t][q] = 0.f;
            }
        }
    }

    // ================= phase 2: y = t @ Wfc =====================================
    {
        const __half* wp_base = wt + (size_t)3 * 16384;
        for (int kc = 0; kc < 4; kc++) {
            __syncthreads();
            {
                const uint4* ph = (const uint4*)(wp_base + (size_t)(kc * 32 + br) * HD + bc * 16);
                uint4 v0 = __ldg(ph), v1 = __ldg(ph + 1);
                __half* dh = (__half*)(smem + OFF_SB) + br * SB_STR + bc * 16;
                *(uint4*)dh = v0; *(uint4*)(dh + 8) = v1;
            }
            __syncthreads();

            #pragma unroll
            for (int kb2 = 0; kb2 < 32; kb2 += 16) {
                int kb = kc * 32 + kb2;
                uint32_t ahf[2][4];
                #pragma unroll
                for (int mi = 0; mi < 2; mi++) {
                    uint32_t aoff = (uint32_t)((wm * 32 + mi * 16 + lrow) * TB_STR + kb + lcol * 8) * 2;
                    ldsm_x4(ahf[mi], sb + OFF_TBUF + aoff);
                }
                #pragma unroll
                for (int g = 0; g < 4; g++) {
                    uint32_t bh[4];
                    uint32_t boff = (uint32_t)((kb2 + lrow) * SB_STR + wn * 64 + g * 16 + lcol * 8) * 2;
                    ldsm_x4t(bh, sb + OFF_SB + boff);
                    #pragma unroll
                    for (int mi = 0; mi < 2; mi++) {
                        #pragma unroll
                        for (int nj = 0; nj < 2; nj++)
                            mma_f16(acc[mi][g * 2 + nj], ahf[mi], bh[nj * 2], bh[nj * 2 + 1]);
                    }
                }
            }
        }
    }

    // ================= epilogue: ReLU + BN, store ==============================
    #pragma unroll
    for (int mi = 0; mi < 2; mi++) {
        #pragma unroll
        for (int t = 0; t < 8; t++) {
            int g = t >> 1, nj = t & 1;
            int row0 = wm * 32 + mi * 16 + (lane >> 2);
            int col  = wn * 64 + g * 16 + nj * 8 + (lane & 3) * 2;
            float bf0 = bfcs[col], bf1 = bfcs[col + 1];
            float sc0 = scs[col], sc1 = scs[col + 1];
            float sh0 = shs[col], sh1 = shs[col + 1];
            #pragma unroll
            for (int half = 0; half < 2; half++) {
                int node = bn0 + row0 + half * 8;
                if (node < n) {
                    float y0 = fmaxf(acc[mi][t][half * 2]     + bf0, 0.f);
                    float y1 = fmaxf(acc[mi][t][half * 2 + 1] + bf1, 0.f);
                    float v0 = y0 * sc0 + sh0;
                    float v1 = y1 * sc1 + sh1;
                    if (outh) {
                        __half2 hv = __floats2half2_rn(v0, v1);
                        *(uint32_t*)(outh + (size_t)node * HD + col) = *(uint32_t*)&hv;
                    } else {
                        *(float2*)(outf + (size_t)node * HD + col) = make_float2(v0, v1);
                    }
                }
            }
        }
    }
}

// ---------------- launch --------------------------------------------------------
extern "C" void kernel_launch(void* const* d_in, const int* in_sizes, int n_in,
                              void* d_out, int out_size)
{
    const float* x     = (const float*)d_in[0];
    const int* srcs[3] = {(const int*)d_in[1], (const int*)d_in[3], (const int*)d_in[5]};
    const int* dsts[3] = {(const int*)d_in[2], (const int*)d_in[4], (const int*)d_in[6]};
    const float* Wg0   = (const float*)d_in[7];
    const float* bg0   = (const float*)d_in[8];
    const float* Wg1   = (const float*)d_in[9];
    const float* bg1   = (const float*)d_in[10];
    const float* Wfc   = (const float*)d_in[11];
    const float* bfc   = (const float*)d_in[12];
    const float* gamma = (const float*)d_in[13];
    const float* beta  = (const float*)d_in[14];
    const float* mean  = (const float*)d_in[15];
    const float* var   = (const float*)d_in[16];

    int n = in_sizes[0] / HD;
    int es[3] = {in_sizes[1], in_sizes[3], in_sizes[5]};

    int *p_deg, *p_off, *p_cur, *p_csum;
    int2* p_csr;
    float *p_rs;
    __half *p_af, *p_wt, *p_xh, *p_h;
    cudaGetSymbolAddress((void**)&p_deg,  g_deg);
    cudaGetSymbolAddress((void**)&p_rs,   g_rs);
    cudaGetSymbolAddress((void**)&p_off,  g_off);
    cudaGetSymbolAddress((void**)&p_cur,  g_cur);
    cudaGetSymbolAddress((void**)&p_csum, g_csum);
    cudaGetSymbolAddress((void**)&p_csr,  g_csr);
    cudaGetSymbolAddress((void**)&p_af,   g_af);
    cudaGetSymbolAddress((void**)&p_wt,   g_wt);
    cudaGetSymbolAddress((void**)&p_xh,   g_xh);
    cudaGetSymbolAddress((void**)&p_h,    g_h);

    const int NT = 256;
    const int nchunks = (n + 255) / 256;

    cudaFuncSetAttribute(mma_layer_kernel, cudaFuncAttributeMaxDynamicSharedMemorySize, SMEM_TOT);

    // 0) convert x to fp16
    int c4 = n * HD / 4;
    x2h_kernel<<<(c4 + NT - 1) / NT, NT>>>(x, p_xh, c4);

    // 1) degrees -> rsqrt normalizers
    zero_int_kernel<<<(6 * n + NT - 1) / NT, NT>>>(p_deg, 6 * n);
    for (int r = 0; r < 3; r++)
        count_pair_kernel<<<(es[r] + NT - 1) / NT, NT>>>(
            srcs[r], dsts[r], p_deg + (size_t)2 * r * n, p_deg + (size_t)(2 * r + 1) * n, es[r]);
    rs_kernel<<<(6 * n + NT - 1) / NT, NT>>>(p_deg, p_rs, 6 * n);

    // weight prep (tiny)
    prep_weights_kernel<<<512, 256>>>(Wg0, Wg1, Wfc, p_wt);

    // 2) CSR by dst (entries carry rs_out[src]); reused by both layers
    for (int r = 0; r < 3; r++) {
        const int* deg_in = p_deg + (size_t)(2 * r + 1) * n;
        int* off  = p_off  + (size_t)r * (NMAX + 1);
        int* cur  = p_cur  + (size_t)r * NMAX;
        int* csum = p_csum + (size_t)r * 512;
        int2* csr = p_csr  + (size_t)r * EMAX;
        chunk_sum_kernel<<<nchunks, 256>>>(deg_in, csum, n);
        scan_chunks_kernel<<<1, 512>>>(csum, nchunks);
        write_offsets_kernel<<<nchunks, 256>>>(deg_in, csum, off, cur, n);
        csr_fill_kernel<<<(es[r] + NT - 1) / NT, NT>>>(
            srcs[r], dsts[r], p_rs + (size_t)2 * r * n, cur, csr, es[r]);
    }

    // 3) layers
    int mblocks = (n + 127) / 128;
    for (int layer = 0; layer < 2; layer++) {
        const __half* hin = (layer == 0) ? p_xh : p_h;
        for (int r = 0; r < 3; r++) {
            long long thr = (long long)n * 32;
            int blocks = (int)((thr + NT - 1) / NT);
            gather_kernel<<<blocks, NT>>>(hin,
                                          p_csr + (size_t)r * EMAX,
                                          p_off + (size_t)r * (NMAX + 1),
                                          p_rs + (size_t)(2 * r + 1) * n,
                                          p_af + (size_t)r * n * HD, n);
        }
        mma_layer_kernel<<<mblocks, 256, SMEM_TOT>>>(
            p_af,
            p_wt + (size_t)layer * 4 * 16384,
            (layer == 0) ? bg0 : bg1,
            bfc + (size_t)layer * HD,
            gamma + (size_t)layer * HD, beta + (size_t)layer * HD,
            mean + (size_t)layer * HD, var + (size_t)layer * HD,
            (layer == 0) ? nullptr : (float*)d_out,
            (layer == 0) ? p_h : nullptr,
            n);
    }
}